// round 14
// baseline (speedup 1.0000x reference)
#include <cuda_runtime.h>
#include <cuda_fp16.h>
#include <math.h>
#include <stdint.h>

#define SEQ 2048
#define DIM 2048
#define NH 16
#define HDIM 128
#define HIDN 8192
#define EPSV 1e-6f
#define LAMB0 0.8f

typedef __half fp16;

// ---------------- scratch ----------------
__device__ float g_h0f[SEQ * DIM];
__device__ float g_hf [SEQ * DIM];
__device__ float g_lam[NH];

__device__ fp16 g_h0a[SEQ*DIM];
__device__ fp16 g_za [SEQ*DIM];
__device__ fp16 g_qk [(size_t)4*SEQ*DIM];
__device__ fp16 g_vt [SEQ*DIM];
__device__ fp16 g_o1 [SEQ*DIM], g_o2[SEQ*DIM];
__device__ fp16 g_oa [SEQ*DIM];
__device__ fp16 g_g1h[(size_t)SEQ*HIDN];
__device__ fp16 g_ua [(size_t)SEQ*HIDN];
__device__ fp16 g_fwqkv[(size_t)5*DIM*DIM];
__device__ fp16 g_fwo [DIM*DIM];
__device__ fp16 g_fw12[(size_t)2*DIM*HIDN];
__device__ fp16 g_fw3[(size_t)DIM*HIDN];

// ---------------- helpers ----------------
__device__ __forceinline__ uint32_t smem_u32(const void* p) {
    uint32_t a;
    asm("{ .reg .u64 t; cvta.to.shared.u64 t, %1; cvt.u32.u64 %0, t; }" : "=r"(a) : "l"(p));
    return a;
}
__device__ __forceinline__ void cpa16(uint32_t s, const void* g) {
    asm volatile("cp.async.cg.shared.global [%0], [%1], 16;" :: "r"(s), "l"(g));
}
#define CP_COMMIT() asm volatile("cp.async.commit_group;")
#define CP_WAIT(n)  asm volatile("cp.async.wait_group %0;" :: "n"(n))

__device__ __forceinline__ void ldm4(uint32_t* r, uint32_t addr) {
    asm volatile("ldmatrix.sync.aligned.m8n8.x4.shared.b16 {%0,%1,%2,%3}, [%4];"
        : "=r"(r[0]), "=r"(r[1]), "=r"(r[2]), "=r"(r[3]) : "r"(addr));
}
__device__ __forceinline__ void mma_hf(float* d, const uint32_t* a, uint32_t b0, uint32_t b1) {
    asm volatile("mma.sync.aligned.m16n8k16.row.col.f32.f16.f16.f32 "
        "{%0,%1,%2,%3}, {%4,%5,%6,%7}, {%8,%9}, {%0,%1,%2,%3};"
        : "+f"(d[0]), "+f"(d[1]), "+f"(d[2]), "+f"(d[3])
        : "r"(a[0]), "r"(a[1]), "r"(a[2]), "r"(a[3]), "r"(b0), "r"(b1));
}

// FMA-pipe exp
__device__ __forceinline__ float fexp(float x) {
    float y = x * 1.44269504089f;
    y = fmaxf(fminf(y, 126.0f), -125.0f);
    float z = __fadd_rn(y, 12582912.0f);
    float n = __fsub_rn(z, 12582912.0f);
    float f = __fsub_rn(y, n);
    float p =            1.33335581e-3f;
    p = fmaf(p, f, 9.61812911e-3f);
    p = fmaf(p, f, 5.55041087e-2f);
    p = fmaf(p, f, 2.40226507e-1f);
    p = fmaf(p, f, 6.93147181e-1f);
    p = fmaf(p, f, 1.0f);
    int i = __float_as_int(z);
    float s = __int_as_float((i << 23) + 0x3F800000);
    return p * s;
}

// ---------------- fp16 GEMM: 256x128 tile, 8 warps of 64x64 ----------------
// MODE 0: fp32 (+residual Rf). MODE 2: fp16. MODE 3: fp16 = silu(Rh)*acc.
template <int MODE>
__global__ __launch_bounds__(256) void mma_gemm(
    const fp16* __restrict__ Ah, int lda, long sA,
    const fp16* __restrict__ B, int ldb, long sB,
    float* __restrict__ Cf, const float* __restrict__ Rf, const fp16* __restrict__ Rh,
    fp16* __restrict__ Ch,
    int ldc, long sC, int K, float alpha)
{
    constexpr int RSB  = 80;                 // 32 fp16 + 8B pad
    constexpr int ABYTES = 256 * RSB;        // 20480
    constexpr int STG  = ABYTES + 128 * RSB; // 30720
    extern __shared__ __align__(128) char dsm[];
    const uint32_t sb = smem_u32(dsm);

    const int tid = threadIdx.x;
    const int m0 = blockIdx.y * 256, n0 = blockIdx.x * 128, z = blockIdx.z;

    Ah += (long)z * sA + (long)m0 * lda;
    B  += (long)z * sB + (long)n0 * ldb;

    const int NC = K >> 5;   // KC = 32

    auto load_chunk = [&](int c, int s) {
        const long k0 = (long)c << 5;
        const uint32_t st = sb + (uint32_t)s * STG;
        #pragma unroll
        for (int i = 0; i < 6; i++) {
            int idx = tid + 256 * i;        // 0..1535
            int row = idx >> 2;             // 0..383
            int sg  = idx & 3;
            uint32_t so = st + (uint32_t)row * RSB + (uint32_t)sg * 16;
            if (row < 256) cpa16(so, Ah + (long)row * lda + k0 + sg * 8);
            else           cpa16(so, B + (long)(row - 256) * ldb + k0 + sg * 8);
        }
    };

    const int l  = tid & 31;
    const int wp = tid >> 5;
    const int wm = (wp >> 1) * 64;          // 4 M-groups
    const int wn = (wp & 1) * 64;           // 2 N-groups
    const uint32_t aoff = (uint32_t)(wm + (l & 15)) * RSB + (uint32_t)((l >> 4) * 16);
    const uint32_t boff = (uint32_t)ABYTES + (uint32_t)(wn + (l & 7) + ((l >> 4) << 3)) * RSB
                        + (uint32_t)(((l >> 3) & 1) * 16);

    float acc[4][8][4];
    #pragma unroll
    for (int a = 0; a < 4; a++)
        #pragma unroll
        for (int b = 0; b < 8; b++)
            #pragma unroll
            for (int c = 0; c < 4; c++) acc[a][b][c] = 0.f;

    load_chunk(0, 0); CP_COMMIT();
    load_chunk(1, 1); CP_COMMIT();
    load_chunk(2, 2); CP_COMMIT();

    for (int c = 0; c < NC; c++) {
        const int s = c & 3;
        const int rem = NC - 1 - c;
        if (rem >= 2)      { CP_WAIT(2); }
        else if (rem == 1) { CP_WAIT(1); }
        else               { CP_WAIT(0); }
        __syncthreads();
        if (c + 3 < NC) { load_chunk(c + 3, (c + 3) & 3); CP_COMMIT(); }

        const uint32_t stg = sb + (uint32_t)s * STG;
        #pragma unroll
        for (int ks = 0; ks < 2; ks++) {
            const uint32_t base = stg + (uint32_t)ks * 32;
            uint32_t ah[4][4], bh[4][4];
            #pragma unroll
            for (int mi = 0; mi < 4; mi++)
                ldm4(ah[mi], base + aoff + (uint32_t)mi * (16 * RSB));
            #pragma unroll
            for (int ng = 0; ng < 4; ng++)
                ldm4(bh[ng], base + boff + (uint32_t)ng * (16 * RSB));
            #pragma unroll
            for (int mi = 0; mi < 4; mi++)
                #pragma unroll
                for (int ni = 0; ni < 8; ni++)
                    mma_hf(acc[mi][ni], ah[mi],
                           bh[ni >> 1][(ni & 1) * 2], bh[ni >> 1][(ni & 1) * 2 + 1]);
        }
    }

    const int qr = l >> 2;
    const int qc = (l & 3) * 2;
    const long cbase = (long)z * sC + (long)m0 * ldc + n0;
    #pragma unroll
    for (int mi = 0; mi < 4; mi++)
        #pragma unroll
        for (int ni = 0; ni < 8; ni++)
            #pragma unroll
            for (int hr = 0; hr < 2; hr++) {
                long off = cbase + (long)(wm + mi * 16 + qr + hr * 8) * ldc + (wn + ni * 8 + qc);
                float v0 = acc[mi][ni][hr * 2 + 0] * alpha;
                float v1 = acc[mi][ni][hr * 2 + 1] * alpha;
                if (MODE == 0) {
                    if (Rf) { v0 += Rf[off]; v1 += Rf[off + 1]; }
                    Cf[off] = v0; Cf[off + 1] = v1;
                } else if (MODE == 2) {
                    Ch[off]     = __float2half(v0);
                    Ch[off + 1] = __float2half(v1);
                } else {
                    float a0 = __half2float(Rh[off]),     s0 = a0 / (1.f + fexp(-a0));
                    float a1 = __half2float(Rh[off + 1]), s1 = a1 / (1.f + fexp(-a1));
                    Ch[off]     = __float2half(s0 * v0);
                    Ch[off + 1] = __float2half(s1 * v1);
                }
            }
}

// ---------------- single-branch flash attention (unchanged) ----------------
__global__ __launch_bounds__(256, 1) void flash_branch(
    const fp16* __restrict__ qg, const fp16* __restrict__ kg,
    const fp16* __restrict__ vtg, fp16* __restrict__ ob)
{
    extern __shared__ __align__(128) char dsm[];
    const uint32_t sb = smem_u32(dsm);
    const int tid = threadIdx.x;
    const int l = tid & 31, w = tid >> 5;
    const int m0 = blockIdx.x * 128;
    const int h  = blockIdx.y;

    {
        const fp16* gq = qg + (long)m0 * DIM + h * HDIM;
        #pragma unroll
        for (int i = 0; i < 8; i++) {
            int idx = tid + i * 256;
            int row = idx >> 4, j = idx & 15;
            cpa16(sb + (uint32_t)row * 256 + (uint32_t)((j ^ (row & 7)) << 4),
                  gq + (long)row * DIM + j * 8);
        }
    }

    auto load_stage = [&](int kt, int s) {
        const uint32_t st = sb + 32768 + (uint32_t)s * 32768;
        const int kb = kt * 64;
        const fp16* gk = kg + (long)kb * DIM + h * HDIM;
        #pragma unroll
        for (int i = 0; i < 4; i++) {
            int idx = tid + i * 256;
            int row = idx >> 4, j = idx & 15;
            cpa16(st + (uint32_t)row * 256 + (uint32_t)((j ^ (row & 7)) << 4),
                  gk + (long)row * DIM + j * 8);
        }
        const fp16* gv = vtg + (long)(h * HDIM) * SEQ + kb;
        #pragma unroll
        for (int i = 0; i < 4; i++) {
            int idx = tid + i * 256;
            int row = idx >> 3, j = idx & 7;
            cpa16(st + 16384 + (uint32_t)row * 128 + (uint32_t)((j ^ (row & 7)) << 4),
                  gv + (long)row * SEQ + j * 8);
        }
    };
    load_stage(0, 0); CP_COMMIT();
    load_stage(1, 1); CP_COMMIT();

    const int arow = w * 16 + (l & 15);
    const int axor = arow & 7;
    const int alo  = l >> 4;
    const uint32_t aQ = sb + (uint32_t)arow * 256;
    const int bn  = (l & 7) + ((l >> 4) << 3);
    const int bko = (l >> 3) & 1;
    const int bxor = bn & 7;

    float m0s = -1e30f, m1s = -1e30f, l0s = 0.f, l1s = 0.f;
    float O[16][4];
    #pragma unroll
    for (int d = 0; d < 16; d++)
        #pragma unroll
        for (int e = 0; e < 4; e++) O[d][e] = 0.f;

    const float qksc = 0.08838834764831845f;

    #pragma unroll 1
    for (int kt = 0; kt < 32; kt++) {
        CP_WAIT(1);
        __syncthreads();
        const uint32_t st = sb + 32768 + (uint32_t)(kt & 1) * 32768;

        float sa[8][4];
        #pragma unroll
        for (int i = 0; i < 8; i++)
            #pragma unroll
            for (int e = 0; e < 4; e++) sa[i][e] = 0.f;
        {
            uint32_t qa[8][4];
            #pragma unroll
            for (int t = 0; t < 8; t++)
                ldm4(qa[t], aQ + (uint32_t)(((2*t + alo) ^ axor) << 4));
            #pragma unroll
            for (int ng = 0; ng < 4; ng++) {
                const uint32_t krow = st + (uint32_t)(ng*16 + bn) * 256;
                #pragma unroll
                for (int t = 0; t < 8; t++) {
                    uint32_t bf[4];
                    ldm4(bf, krow + (uint32_t)(((2*t + bko) ^ bxor) << 4));
                    mma_hf(sa[2*ng],   qa[t], bf[0], bf[1]);
                    mma_hf(sa[2*ng+1], qa[t], bf[2], bf[3]);
                }
            }
        }

        float rm0 = -1e30f, rm1 = -1e30f;
        #pragma unroll
        for (int i = 0; i < 8; i++) {
            #pragma unroll
            for (int e = 0; e < 4; e++) sa[i][e] *= qksc;
            rm0 = fmaxf(rm0, fmaxf(sa[i][0], sa[i][1]));
            rm1 = fmaxf(rm1, fmaxf(sa[i][2], sa[i][3]));
        }
        rm0 = fmaxf(rm0, __shfl_xor_sync(0xffffffffu, rm0, 1));
        rm0 = fmaxf(rm0, __shfl_xor_sync(0xffffffffu, rm0, 2));
        rm1 = fmaxf(rm1, __shfl_xor_sync(0xffffffffu, rm1, 1));
        rm1 = fmaxf(rm1, __shfl_xor_sync(0xffffffffu, rm1, 2));
        const float mn0 = fmaxf(m0s, rm0), mn1 = fmaxf(m1s, rm1);
        const float c0 = fexp(m0s - mn0), c1 = fexp(m1s - mn1);
        #pragma unroll
        for (int d = 0; d < 16; d++) {
            O[d][0] *= c0; O[d][1] *= c0;
            O[d][2] *= c1; O[d][3] *= c1;
        }
        float ps0 = 0.f, ps1 = 0.f;
        #pragma unroll
        for (int i = 0; i < 8; i++) {
            sa[i][0] = fexp(sa[i][0] - mn0); ps0 += sa[i][0];
            sa[i][1] = fexp(sa[i][1] - mn0); ps0 += sa[i][1];
            sa[i][2] = fexp(sa[i][2] - mn1); ps1 += sa[i][2];
            sa[i][3] = fexp(sa[i][3] - mn1); ps1 += sa[i][3];
        }
        ps0 += __shfl_xor_sync(0xffffffffu, ps0, 1);
        ps0 += __shfl_xor_sync(0xffffffffu, ps0, 2);
        ps1 += __shfl_xor_sync(0xffffffffu, ps1, 1);
        ps1 += __shfl_xor_sync(0xffffffffu, ps1, 2);
        l0s = l0s * c0 + ps0;  m0s = mn0;
        l1s = l1s * c1 + ps1;  m1s = mn1;

        uint32_t pf[4][4];
        #pragma unroll
        for (int t = 0; t < 4; t++) {
            __half2 h0 = __floats2half2_rn(sa[2*t][0],   sa[2*t][1]);
            __half2 h1 = __floats2half2_rn(sa[2*t][2],   sa[2*t][3]);
            __half2 h2 = __floats2half2_rn(sa[2*t+1][0], sa[2*t+1][1]);
            __half2 h3 = __floats2half2_rn(sa[2*t+1][2], sa[2*t+1][3]);
            pf[t][0] = *(uint32_t*)&h0; pf[t][1] = *(uint32_t*)&h1;
            pf[t][2] = *(uint32_t*)&h2; pf[t][3] = *(uint32_t*)&h3;
        }

        const uint32_t vst = st + 16384;
        #pragma unroll
        for (int dg = 0; dg < 8; dg++) {
            const uint32_t vrow = vst + (uint32_t)(dg*16 + bn) * 128;
            #pragma unroll
            for (int t = 0; t < 4; t++) {
                uint32_t bf[4];
                ldm4(bf, vrow + (uint32_t)(((2*t + bko) ^ bxor) << 4));
                mma_hf(O[2*dg],   pf[t], bf[0], bf[1]);
                mma_hf(O[2*dg+1], pf[t], bf[2], bf[3]);
            }
        }
        __syncthreads();
        if (kt + 2 < 32) load_stage(kt + 2, kt & 1);
        CP_COMMIT();
    }

    const float i0 = 1.f / l0s, i1 = 1.f / l1s;
    const int r0 = m0 + w * 16 + (l >> 2);
    #pragma unroll
    for (int d = 0; d < 16; d++) {
        const int col = h * HDIM + d * 8 + 2 * (l & 3);
        __half2 p0 = __floats2half2_rn(O[d][0] * i0, O[d][1] * i0);
        __half2 p1 = __floats2half2_rn(O[d][2] * i1, O[d][3] * i1);
        *(uint32_t*)&ob[(long)r0 * DIM + col]       = *(uint32_t*)&p0;
        *(uint32_t*)&ob[(long)(r0 + 8) * DIM + col] = *(uint32_t*)&p1;
    }
}

// ---------------- combine: oa = o1 - lam[h]*o2 ----------------
__global__ __launch_bounds__(256) void combine_kernel(
    const fp16* __restrict__ o1, const fp16* __restrict__ o2,
    const float* __restrict__ lam, fp16* __restrict__ oa)
{
    long i = (long)blockIdx.x * 256 + threadIdx.x;
    int h = (int)((i * 2) % DIM) / HDIM;
    float lm = lam[h];
    __half2 a = ((const __half2*)o1)[i];
    __half2 b = ((const __half2*)o2)[i];
    float2 af = __half22float2(a), bf = __half22float2(b);
    __half2 r = __floats2half2_rn(af.x - lm * bf.x, af.y - lm * bf.y);
    ((__half2*)oa)[i] = r;
}

// ---------------- batched QKV weight transpose ----------------
__global__ __launch_bounds__(256) void wt5_kernel(
    const float* __restrict__ w0, const float* __restrict__ w1,
    const float* __restrict__ w2, const float* __restrict__ w3,
    const float* __restrict__ w4, fp16* __restrict__ outb)
{
    const int z = blockIdx.z;
    const int m = z >> 4, h = z & 15;
    const float* in = (m == 0 ? w0 : m == 1 ? w1 : m == 2 ? w2 : m == 3 ? w3 : w4)
                    + (long)h * DIM * HDIM;
    fp16* oh = outb + (long)m * DIM * DIM + (long)h * HDIM * DIM;
    const int c0 = blockIdx.x * 32, r0 = blockIdx.y * 32;
    __shared__ float t[32][33];
    const int tx = threadIdx.x & 31, ty = threadIdx.x >> 5;
    #pragma unroll
    for (int i = 0; i < 4; i++)
        t[ty + 8*i][tx] = in[(long)(r0 + ty + 8*i) * HDIM + c0 + tx];
    __syncthreads();
    #pragma unroll
    for (int i = 0; i < 4; i++)
        oh[(long)(c0 + ty + 8*i) * DIM + r0 + tx] = __float2half(t[tx][ty + 8*i]);
}

// ---------------- generic transpose fp32->fp16 ----------------
__global__ __launch_bounds__(256) void transpose_half2(
    const float* __restrict__ inA, const float* __restrict__ inB,
    fp16* __restrict__ outb, int R, int C)
{
    const int z = blockIdx.z;
    const float* in = (z == 0) ? inA : inB;
    fp16* oh = outb + (long)z * R * C;
    const int c0 = blockIdx.x * 32, r0 = blockIdx.y * 32;
    __shared__ float t[32][33];
    const int tx = threadIdx.x & 31, ty = threadIdx.x >> 5;
    #pragma unroll
    for (int i = 0; i < 4; i++)
        t[ty + 8*i][tx] = in[(long)(r0 + ty + 8*i) * C + c0 + tx];
    __syncthreads();
    #pragma unroll
    for (int i = 0; i < 4; i++)
        oh[(long)(c0 + ty + 8*i) * R + r0 + tx] = __float2half(t[tx][ty + 8*i]);
}

// ---------------- RMSNorm ----------------
__global__ __launch_bounds__(256) void rmsnorm_kernel(const float* __restrict__ x,
                                                      const float* __restrict__ g,
                                                      float* __restrict__ yf,
                                                      fp16* __restrict__ ya) {
    __shared__ float sh[8];
    const long row = blockIdx.x;
    const float* xr = x + row * (long)DIM;
    float v[8], ss = 0.f;
    #pragma unroll
    for (int i = 0; i < 8; i++) { v[i] = xr[threadIdx.x + 256*i]; ss += v[i]*v[i]; }
    #pragma unroll
    for (int o = 16; o; o >>= 1) ss += __shfl_xor_sync(0xffffffffu, ss, o);
    if ((threadIdx.x & 31) == 0) sh[threadIdx.x >> 5] = ss;
    __syncthreads();
    float tot = 0.f;
    #pragma unroll
    for (int i = 0; i < 8; i++) tot += sh[i];
    const float sc = rsqrtf(tot * (1.0f / DIM) + EPSV);
    #pragma unroll
    for (int i = 0; i < 8; i++) {
        int c = threadIdx.x + 256*i;
        float y = v[i] * sc * g[c];
        long o = row * (long)DIM + c;
        if (yf) yf[o] = y;
        ya[o] = __float2half(y);
    }
}

// ---------------- lambda ----------------
__global__ void lambda_kernel(const float* __restrict__ lq1, const float* __restrict__ lk1,
                              const float* __restrict__ lq2, const float* __restrict__ lk2,
                              float* __restrict__ lam) {
    __shared__ float s1[128], s2[128];
    int h = blockIdx.x, t = threadIdx.x;
    int i = h * HDIM + t;
    s1[t] = lq1[i] * lk1[i];
    s2[t] = lq2[i] * lk2[i];
    __syncthreads();
    for (int o = 64; o; o >>= 1) {
        if (t < o) { s1[t] += s1[t+o]; s2[t] += s2[t+o]; }
        __syncthreads();
    }
    if (t == 0) lam[h] = expf(s1[0]) - expf(s2[0]) + LAMB0;
}

// ---------------- launcher ----------------
extern "C" void kernel_launch(void* const* d_in, const int* in_sizes, int n_in,
                              void* d_out, int out_size) {
    (void)in_sizes; (void)n_in; (void)out_size;
    const float* x   = (const float*)d_in[0];
    const float* gn  = (const float*)d_in[1];
    const float* Wq1 = (const float*)d_in[2];
    const float* Wq2 = (const float*)d_in[3];
    const float* Wk1 = (const float*)d_in[4];
    const float* Wk2 = (const float*)d_in[5];
    const float* Wv  = (const float*)d_in[6];
    const float* lq1 = (const float*)d_in[7];
    const float* lk1 = (const float*)d_in[8];
    const float* lq2 = (const float*)d_in[9];
    const float* lk2 = (const float*)d_in[10];
    const float* Wo  = (const float*)d_in[11];
    const float* W1  = (const float*)d_in[12];
    const float* W2  = (const float*)d_in[13];
    const float* W3  = (const float*)d_in[14];
    float* out = (float*)d_out;

    const int SMEM  = 4 * 30720;         // 122880 (GEMM)
    const int FSMEM = 32768 + 2 * 32768; // 98304 (flash)
    cudaFuncSetAttribute(mma_gemm<0>, cudaFuncAttributeMaxDynamicSharedMemorySize, SMEM);
    cudaFuncSetAttribute(mma_gemm<2>, cudaFuncAttributeMaxDynamicSharedMemorySize, SMEM);
    cudaFuncSetAttribute(mma_gemm<3>, cudaFuncAttributeMaxDynamicSharedMemorySize, SMEM);
    cudaFuncSetAttribute(flash_branch, cudaFuncAttributeMaxDynamicSharedMemorySize, FSMEM);

#define SYM(v, s) cudaGetSymbolAddress((void**)&v, s)
    float *h0f, *hf, *lam;
    SYM(h0f, g_h0f); SYM(hf, g_hf); SYM(lam, g_lam);
    fp16 *h0a,*za,*qk,*vt,*o1,*o2,*oa,*g1h,*ua;
    fp16 *fwqkv,*fwo,*fw12,*fw3;
    SYM(h0a, g_h0a); SYM(za, g_za); SYM(qk, g_qk); SYM(vt, g_vt);
    SYM(o1, g_o1); SYM(o2, g_o2); SYM(oa, g_oa); SYM(g1h, g_g1h); SYM(ua, g_ua);
    SYM(fwqkv, g_fwqkv); SYM(fwo, g_fwo); SYM(fw12, g_fw12); SYM(fw3, g_fw3);
#undef SYM

    const long SD = (long)SEQ * DIM;
    const long DD = (long)DIM * DIM;
    fp16* q1 = qk;
    fp16* q2 = qk + SD;
    fp16* k1 = qk + 2 * SD;
    fp16* k2 = qk + 3 * SD;
    fp16* fwv = fwqkv + 4 * DD;
    fp16* fw1 = fw12;
    fp16* fw2 = fw12 + (long)DIM * HIDN;

    // ---- pre-flash: 5 launches ----
    dim3 g5(HDIM/32, DIM/32, 5 * NH);
    wt5_kernel<<<g5, 256>>>(Wq1, Wq2, Wk1, Wk2, Wv, fwqkv);
    rmsnorm_kernel<<<SEQ, 256>>>(x, gn, h0f, h0a);
    dim3 gproj(DIM/128, SEQ/256, 4);
    mma_gemm<2><<<gproj, 256, SMEM>>>(h0a, DIM, 0, fwqkv, DIM, DD, nullptr, nullptr, nullptr, qk, DIM, SD, DIM, 1.f);
    dim3 gvt(SEQ/128, DIM/256, 1);
    mma_gemm<2><<<gvt, 256, SMEM>>>(fwv, DIM, 0, h0a, DIM, 0, nullptr, nullptr, nullptr, vt, SEQ, 0, DIM, 1.f);
    dim3 gfl(SEQ/128, NH);
    flash_branch<<<gfl, 256, FSMEM>>>(q1, k1, vt, o1);
    flash_branch<<<gfl, 256, FSMEM>>>(q2, k2, vt, o2);

    lambda_kernel<<<NH, 128>>>(lq1, lk1, lq2, lk2, lam);
    combine_kernel<<<(SEQ * DIM / 2) / 256, 256>>>(o1, o2, lam, oa);

    dim3 gtO(DIM/32, DIM/32, 1);
    transpose_half2<<<gtO, 256>>>(Wo, Wo, fwo, DIM, DIM);
    dim3 gwo(DIM/128, SEQ/256, 1);
    mma_gemm<0><<<gwo, 256, SMEM>>>(oa, DIM, 0, fwo, DIM, 0, hf, h0f, nullptr, nullptr, DIM, 0, DIM, 1.f);

    rmsnorm_kernel<<<SEQ, 256>>>(hf, gn, nullptr, za);

    dim3 gt12(HIDN/32, DIM/32, 2);
    transpose_half2<<<gt12, 256>>>(W1, W2, fw12, DIM, HIDN);
    dim3 gt3(DIM/32, HIDN/32, 1);
    transpose_half2<<<gt3, 256>>>(W3, W3, fw3, HIDN, DIM);

    dim3 gffn(HIDN/128, SEQ/256, 1);
    mma_gemm<2><<<gffn, 256, SMEM>>>(za, DIM, 0, fw1, DIM, 0, nullptr, nullptr, nullptr, g1h, HIDN, 0, DIM, 1.f);
    mma_gemm<3><<<gffn, 256, SMEM>>>(za, DIM, 0, fw2, DIM, 0, nullptr, nullptr, g1h, ua, HIDN, 0, DIM, 1.f);

    dim3 gw3(DIM/128, SEQ/256, 1);
    mma_gemm<0><<<gw3, 256, SMEM>>>(ua, HIDN, 0, fw3, HIDN, 0, out, hf, nullptr, nullptr, DIM, 0, HIDN, 1.f);
}

// round 15
// speedup vs baseline: 1.1757x; 1.1757x over previous
#include <cuda_runtime.h>
#include <cuda_fp16.h>
#include <math.h>
#include <stdint.h>

#define SEQ 2048
#define DIM 2048
#define NH 16
#define HDIM 128
#define HIDN 8192
#define EPSV 1e-6f
#define LAMB0 0.8f

typedef __half fp16;

// ---------------- scratch ----------------
__device__ float g_h0f[SEQ * DIM];
__device__ float g_hf [SEQ * DIM];
__device__ float g_lam[NH];

__device__ fp16 g_h0a[SEQ*DIM];
__device__ fp16 g_za [SEQ*DIM];
__device__ fp16 g_qk [(size_t)4*SEQ*DIM];
__device__ fp16 g_vt [SEQ*DIM];
__device__ fp16 g_o1 [SEQ*DIM], g_o2[SEQ*DIM];
__device__ fp16 g_oa [SEQ*DIM];
__device__ fp16 g_g1h[(size_t)SEQ*HIDN];
__device__ fp16 g_ua [(size_t)SEQ*HIDN];
__device__ fp16 g_fwqkv[(size_t)5*DIM*DIM];
__device__ fp16 g_fwo [DIM*DIM];
__device__ fp16 g_fw12[(size_t)2*DIM*HIDN];
__device__ fp16 g_fw3[(size_t)DIM*HIDN];

// ---------------- helpers ----------------
__device__ __forceinline__ uint32_t smem_u32(const void* p) {
    uint32_t a;
    asm("{ .reg .u64 t; cvta.to.shared.u64 t, %1; cvt.u32.u64 %0, t; }" : "=r"(a) : "l"(p));
    return a;
}
__device__ __forceinline__ void cpa16(uint32_t s, const void* g) {
    asm volatile("cp.async.cg.shared.global [%0], [%1], 16;" :: "r"(s), "l"(g));
}
#define CP_COMMIT() asm volatile("cp.async.commit_group;")
#define CP_WAIT(n)  asm volatile("cp.async.wait_group %0;" :: "n"(n))

__device__ __forceinline__ void ldm4(uint32_t* r, uint32_t addr) {
    asm volatile("ldmatrix.sync.aligned.m8n8.x4.shared.b16 {%0,%1,%2,%3}, [%4];"
        : "=r"(r[0]), "=r"(r[1]), "=r"(r[2]), "=r"(r[3]) : "r"(addr));
}
__device__ __forceinline__ void mma_hf(float* d, const uint32_t* a, uint32_t b0, uint32_t b1) {
    asm volatile("mma.sync.aligned.m16n8k16.row.col.f32.f16.f16.f32 "
        "{%0,%1,%2,%3}, {%4,%5,%6,%7}, {%8,%9}, {%0,%1,%2,%3};"
        : "+f"(d[0]), "+f"(d[1]), "+f"(d[2]), "+f"(d[3])
        : "r"(a[0]), "r"(a[1]), "r"(a[2]), "r"(a[3]), "r"(b0), "r"(b1));
}

// FMA-pipe exp
__device__ __forceinline__ float fexp(float x) {
    float y = x * 1.44269504089f;
    y = fmaxf(fminf(y, 126.0f), -125.0f);
    float z = __fadd_rn(y, 12582912.0f);
    float n = __fsub_rn(z, 12582912.0f);
    float f = __fsub_rn(y, n);
    float p =            1.33335581e-3f;
    p = fmaf(p, f, 9.61812911e-3f);
    p = fmaf(p, f, 5.55041087e-2f);
    p = fmaf(p, f, 2.40226507e-1f);
    p = fmaf(p, f, 6.93147181e-1f);
    p = fmaf(p, f, 1.0f);
    int i = __float_as_int(z);
    float s = __int_as_float((i << 23) + 0x3F800000);
    return p * s;
}

// ---------------- fp16 GEMM: 128x128 tile, 512 thr, 16 warps of 32x32 ----------------
// 3-stage cp.async ring; regs capped at 64 -> 2 CTAs/SM, 32 warps/SM.
// MODE 0: fp32 (+residual Rf). MODE 2: fp16. MODE 3: fp16 = silu(Rh)*acc.
template <int MODE>
__global__ __launch_bounds__(512, 2) void mma_gemm(
    const fp16* __restrict__ Ah, int lda, long sA,
    const fp16* __restrict__ B, int ldb, long sB,
    float* __restrict__ Cf, const float* __restrict__ Rf, const fp16* __restrict__ Rh,
    fp16* __restrict__ Ch,
    int ldc, long sC, int K, float alpha)
{
    constexpr int RSB    = 80;              // 32 fp16 + 8B pad
    constexpr int ABYTES = 128 * RSB;       // 10240
    constexpr int STG    = 2 * ABYTES;      // 20480 (A + B)
    extern __shared__ __align__(128) char dsm[];
    const uint32_t sb = smem_u32(dsm);

    const int tid = threadIdx.x;
    const int m0 = blockIdx.y * 128, n0 = blockIdx.x * 128, z = blockIdx.z;

    Ah += (long)z * sA + (long)m0 * lda;
    B  += (long)z * sB + (long)n0 * ldb;

    const int NC = K >> 5;   // KC = 32

    auto load_chunk = [&](int c, int s) {
        const long k0 = (long)c << 5;
        const uint32_t st = sb + (uint32_t)s * STG;
        #pragma unroll
        for (int i = 0; i < 2; i++) {
            int idx = tid + 512 * i;        // 0..1023
            int row = idx >> 2;             // 0..255
            int sg  = idx & 3;
            uint32_t so = st + (uint32_t)row * RSB + (uint32_t)sg * 16;
            if (row < 128) cpa16(so, Ah + (long)row * lda + k0 + sg * 8);
            else           cpa16(so, B + (long)(row - 128) * ldb + k0 + sg * 8);
        }
    };

    const int l  = tid & 31;
    const int wp = tid >> 5;                // 0..15
    const int wm = (wp & 3) * 32;           // 4 M-groups
    const int wn = (wp >> 2) * 32;          // 4 N-groups
    const uint32_t aoff = (uint32_t)(wm + (l & 15)) * RSB + (uint32_t)((l >> 4) * 16);
    const uint32_t boff = (uint32_t)ABYTES + (uint32_t)(wn + (l & 7) + ((l >> 4) << 3)) * RSB
                        + (uint32_t)(((l >> 3) & 1) * 16);

    float acc[2][4][4];
    #pragma unroll
    for (int a = 0; a < 2; a++)
        #pragma unroll
        for (int b = 0; b < 4; b++)
            #pragma unroll
            for (int c = 0; c < 4; c++) acc[a][b][c] = 0.f;

    load_chunk(0, 0); CP_COMMIT();
    load_chunk(1, 1); CP_COMMIT();

    for (int c = 0; c < NC; c++) {
        if (c + 1 < NC) { CP_WAIT(1); }
        else            { CP_WAIT(0); }
        __syncthreads();
        if (c + 2 < NC) {
            int s2 = (c + 2) % 3;
            load_chunk(c + 2, s2);
            CP_COMMIT();
        }

        const uint32_t stg = sb + (uint32_t)(c % 3) * STG;
        #pragma unroll
        for (int ks = 0; ks < 2; ks++) {
            const uint32_t base = stg + (uint32_t)ks * 32;
            uint32_t ah[2][4], bh[2][4];
            #pragma unroll
            for (int mi = 0; mi < 2; mi++)
                ldm4(ah[mi], base + aoff + (uint32_t)mi * (16 * RSB));
            #pragma unroll
            for (int ng = 0; ng < 2; ng++)
                ldm4(bh[ng], base + boff + (uint32_t)ng * (16 * RSB));
            #pragma unroll
            for (int mi = 0; mi < 2; mi++)
                #pragma unroll
                for (int ni = 0; ni < 4; ni++)
                    mma_hf(acc[mi][ni], ah[mi],
                           bh[ni >> 1][(ni & 1) * 2], bh[ni >> 1][(ni & 1) * 2 + 1]);
        }
    }

    const int qr = l >> 2;
    const int qc = (l & 3) * 2;
    const long cbase = (long)z * sC + (long)m0 * ldc + n0;
    #pragma unroll
    for (int mi = 0; mi < 2; mi++)
        #pragma unroll
        for (int ni = 0; ni < 4; ni++)
            #pragma unroll
            for (int hr = 0; hr < 2; hr++) {
                long off = cbase + (long)(wm + mi * 16 + qr + hr * 8) * ldc + (wn + ni * 8 + qc);
                float v0 = acc[mi][ni][hr * 2 + 0] * alpha;
                float v1 = acc[mi][ni][hr * 2 + 1] * alpha;
                if (MODE == 0) {
                    if (Rf) { v0 += Rf[off]; v1 += Rf[off + 1]; }
                    Cf[off] = v0; Cf[off + 1] = v1;
                } else if (MODE == 2) {
                    Ch[off]     = __float2half(v0);
                    Ch[off + 1] = __float2half(v1);
                } else {
                    float a0 = __half2float(Rh[off]),     s0 = a0 / (1.f + fexp(-a0));
                    float a1 = __half2float(Rh[off + 1]), s1 = a1 / (1.f + fexp(-a1));
                    Ch[off]     = __float2half(s0 * v0);
                    Ch[off + 1] = __float2half(s1 * v1);
                }
            }
}

// ---------------- single-branch flash attention (round-13 state) ----------------
__global__ __launch_bounds__(256, 1) void flash_branch(
    const fp16* __restrict__ qg, const fp16* __restrict__ kg,
    const fp16* __restrict__ vtg, fp16* __restrict__ ob)
{
    extern __shared__ __align__(128) char dsm[];
    const uint32_t sb = smem_u32(dsm);
    const int tid = threadIdx.x;
    const int l = tid & 31, w = tid >> 5;
    const int m0 = blockIdx.x * 128;
    const int h  = blockIdx.y;

    {
        const fp16* gq = qg + (long)m0 * DIM + h * HDIM;
        #pragma unroll
        for (int i = 0; i < 8; i++) {
            int idx = tid + i * 256;
            int row = idx >> 4, j = idx & 15;
            cpa16(sb + (uint32_t)row * 256 + (uint32_t)((j ^ (row & 7)) << 4),
                  gq + (long)row * DIM + j * 8);
        }
    }

    auto load_stage = [&](int kt, int s) {
        const uint32_t st = sb + 32768 + (uint32_t)s * 32768;
        const int kb = kt * 64;
        const fp16* gk = kg + (long)kb * DIM + h * HDIM;
        #pragma unroll
        for (int i = 0; i < 4; i++) {
            int idx = tid + i * 256;
            int row = idx >> 4, j = idx & 15;
            cpa16(st + (uint32_t)row * 256 + (uint32_t)((j ^ (row & 7)) << 4),
                  gk + (long)row * DIM + j * 8);
        }
        const fp16* gv = vtg + (long)(h * HDIM) * SEQ + kb;
        #pragma unroll
        for (int i = 0; i < 4; i++) {
            int idx = tid + i * 256;
            int row = idx >> 3, j = idx & 7;
            cpa16(st + 16384 + (uint32_t)row * 128 + (uint32_t)((j ^ (row & 7)) << 4),
                  gv + (long)row * SEQ + j * 8);
        }
    };
    load_stage(0, 0); CP_COMMIT();
    load_stage(1, 1); CP_COMMIT();

    const int arow = w * 16 + (l & 15);
    const int axor = arow & 7;
    const int alo  = l >> 4;
    const uint32_t aQ = sb + (uint32_t)arow * 256;
    const int bn  = (l & 7) + ((l >> 4) << 3);
    const int bko = (l >> 3) & 1;
    const int bxor = bn & 7;

    float m0s = -1e30f, m1s = -1e30f, l0s = 0.f, l1s = 0.f;
    float O[16][4];
    #pragma unroll
    for (int d = 0; d < 16; d++)
        #pragma unroll
        for (int e = 0; e < 4; e++) O[d][e] = 0.f;

    const float qksc = 0.08838834764831845f;

    #pragma unroll 1
    for (int kt = 0; kt < 32; kt++) {
        CP_WAIT(1);
        __syncthreads();
        const uint32_t st = sb + 32768 + (uint32_t)(kt & 1) * 32768;

        float sa[8][4];
        #pragma unroll
        for (int i = 0; i < 8; i++)
            #pragma unroll
            for (int e = 0; e < 4; e++) sa[i][e] = 0.f;
        {
            uint32_t qa[8][4];
            #pragma unroll
            for (int t = 0; t < 8; t++)
                ldm4(qa[t], aQ + (uint32_t)(((2*t + alo) ^ axor) << 4));
            #pragma unroll
            for (int ng = 0; ng < 4; ng++) {
                const uint32_t krow = st + (uint32_t)(ng*16 + bn) * 256;
                #pragma unroll
                for (int t = 0; t < 8; t++) {
                    uint32_t bf[4];
                    ldm4(bf, krow + (uint32_t)(((2*t + bko) ^ bxor) << 4));
                    mma_hf(sa[2*ng],   qa[t], bf[0], bf[1]);
                    mma_hf(sa[2*ng+1], qa[t], bf[2], bf[3]);
                }
            }
        }

        float rm0 = -1e30f, rm1 = -1e30f;
        #pragma unroll
        for (int i = 0; i < 8; i++) {
            #pragma unroll
            for (int e = 0; e < 4; e++) sa[i][e] *= qksc;
            rm0 = fmaxf(rm0, fmaxf(sa[i][0], sa[i][1]));
            rm1 = fmaxf(rm1, fmaxf(sa[i][2], sa[i][3]));
        }
        rm0 = fmaxf(rm0, __shfl_xor_sync(0xffffffffu, rm0, 1));
        rm0 = fmaxf(rm0, __shfl_xor_sync(0xffffffffu, rm0, 2));
        rm1 = fmaxf(rm1, __shfl_xor_sync(0xffffffffu, rm1, 1));
        rm1 = fmaxf(rm1, __shfl_xor_sync(0xffffffffu, rm1, 2));
        const float mn0 = fmaxf(m0s, rm0), mn1 = fmaxf(m1s, rm1);
        const float c0 = fexp(m0s - mn0), c1 = fexp(m1s - mn1);
        #pragma unroll
        for (int d = 0; d < 16; d++) {
            O[d][0] *= c0; O[d][1] *= c0;
            O[d][2] *= c1; O[d][3] *= c1;
        }
        float ps0 = 0.f, ps1 = 0.f;
        #pragma unroll
        for (int i = 0; i < 8; i++) {
            sa[i][0] = fexp(sa[i][0] - mn0); ps0 += sa[i][0];
            sa[i][1] = fexp(sa[i][1] - mn0); ps0 += sa[i][1];
            sa[i][2] = fexp(sa[i][2] - mn1); ps1 += sa[i][2];
            sa[i][3] = fexp(sa[i][3] - mn1); ps1 += sa[i][3];
        }
        ps0 += __shfl_xor_sync(0xffffffffu, ps0, 1);
        ps0 += __shfl_xor_sync(0xffffffffu, ps0, 2);
        ps1 += __shfl_xor_sync(0xffffffffu, ps1, 1);
        ps1 += __shfl_xor_sync(0xffffffffu, ps1, 2);
        l0s = l0s * c0 + ps0;  m0s = mn0;
        l1s = l1s * c1 + ps1;  m1s = mn1;

        uint32_t pf[4][4];
        #pragma unroll
        for (int t = 0; t < 4; t++) {
            __half2 h0 = __floats2half2_rn(sa[2*t][0],   sa[2*t][1]);
            __half2 h1 = __floats2half2_rn(sa[2*t][2],   sa[2*t][3]);
            __half2 h2 = __floats2half2_rn(sa[2*t+1][0], sa[2*t+1][1]);
            __half2 h3 = __floats2half2_rn(sa[2*t+1][2], sa[2*t+1][3]);
            pf[t][0] = *(uint32_t*)&h0; pf[t][1] = *(uint32_t*)&h1;
            pf[t][2] = *(uint32_t*)&h2; pf[t][3] = *(uint32_t*)&h3;
        }

        const uint32_t vst = st + 16384;
        #pragma unroll
        for (int dg = 0; dg < 8; dg++) {
            const uint32_t vrow = vst + (uint32_t)(dg*16 + bn) * 128;
            #pragma unroll
            for (int t = 0; t < 4; t++) {
                uint32_t bf[4];
                ldm4(bf, vrow + (uint32_t)(((2*t + bko) ^ bxor) << 4));
                mma_hf(O[2*dg],   pf[t], bf[0], bf[1]);
                mma_hf(O[2*dg+1], pf[t], bf[2], bf[3]);
            }
        }
        __syncthreads();
        if (kt + 2 < 32) load_stage(kt + 2, kt & 1);
        CP_COMMIT();
    }

    const float i0 = 1.f / l0s, i1 = 1.f / l1s;
    const int r0 = m0 + w * 16 + (l >> 2);
    #pragma unroll
    for (int d = 0; d < 16; d++) {
        const int col = h * HDIM + d * 8 + 2 * (l & 3);
        __half2 p0 = __floats2half2_rn(O[d][0] * i0, O[d][1] * i0);
        __half2 p1 = __floats2half2_rn(O[d][2] * i1, O[d][3] * i1);
        *(uint32_t*)&ob[(long)r0 * DIM + col]       = *(uint32_t*)&p0;
        *(uint32_t*)&ob[(long)(r0 + 8) * DIM + col] = *(uint32_t*)&p1;
    }
}

// ---------------- combine ----------------
__global__ __launch_bounds__(256) void combine_kernel(
    const fp16* __restrict__ o1, const fp16* __restrict__ o2,
    const float* __restrict__ lam, fp16* __restrict__ oa)
{
    long i = (long)blockIdx.x * 256 + threadIdx.x;
    int h = (int)((i * 2) % DIM) / HDIM;
    float lm = lam[h];
    __half2 a = ((const __half2*)o1)[i];
    __half2 b = ((const __half2*)o2)[i];
    float2 af = __half22float2(a), bf = __half22float2(b);
    __half2 r = __floats2half2_rn(af.x - lm * bf.x, af.y - lm * bf.y);
    ((__half2*)oa)[i] = r;
}

// ---------------- batched QKV weight transpose ----------------
__global__ __launch_bounds__(256) void wt5_kernel(
    const float* __restrict__ w0, const float* __restrict__ w1,
    const float* __restrict__ w2, const float* __restrict__ w3,
    const float* __restrict__ w4, fp16* __restrict__ outb)
{
    const int z = blockIdx.z;
    const int m = z >> 4, h = z & 15;
    const float* in = (m == 0 ? w0 : m == 1 ? w1 : m == 2 ? w2 : m == 3 ? w3 : w4)
                    + (long)h * DIM * HDIM;
    fp16* oh = outb + (long)m * DIM * DIM + (long)h * HDIM * DIM;
    const int c0 = blockIdx.x * 32, r0 = blockIdx.y * 32;
    __shared__ float t[32][33];
    const int tx = threadIdx.x & 31, ty = threadIdx.x >> 5;
    #pragma unroll
    for (int i = 0; i < 4; i++)
        t[ty + 8*i][tx] = in[(long)(r0 + ty + 8*i) * HDIM + c0 + tx];
    __syncthreads();
    #pragma unroll
    for (int i = 0; i < 4; i++)
        oh[(long)(c0 + ty + 8*i) * DIM + r0 + tx] = __float2half(t[tx][ty + 8*i]);
}

// ---------------- generic transpose fp32->fp16 ----------------
__global__ __launch_bounds__(256) void transpose_half2(
    const float* __restrict__ inA, const float* __restrict__ inB,
    fp16* __restrict__ outb, int R, int C)
{
    const int z = blockIdx.z;
    const float* in = (z == 0) ? inA : inB;
    fp16* oh = outb + (long)z * R * C;
    const int c0 = blockIdx.x * 32, r0 = blockIdx.y * 32;
    __shared__ float t[32][33];
    const int tx = threadIdx.x & 31, ty = threadIdx.x >> 5;
    #pragma unroll
    for (int i = 0; i < 4; i++)
        t[ty + 8*i][tx] = in[(long)(r0 + ty + 8*i) * C + c0 + tx];
    __syncthreads();
    #pragma unroll
    for (int i = 0; i < 4; i++)
        oh[(long)(c0 + ty + 8*i) * R + r0 + tx] = __float2half(t[tx][ty + 8*i]);
}

// ---------------- RMSNorm ----------------
__global__ __launch_bounds__(256) void rmsnorm_kernel(const float* __restrict__ x,
                                                      const float* __restrict__ g,
                                                      float* __restrict__ yf,
                                                      fp16* __restrict__ ya) {
    __shared__ float sh[8];
    const long row = blockIdx.x;
    const float* xr = x + row * (long)DIM;
    float v[8], ss = 0.f;
    #pragma unroll
    for (int i = 0; i < 8; i++) { v[i] = xr[threadIdx.x + 256*i]; ss += v[i]*v[i]; }
    #pragma unroll
    for (int o = 16; o; o >>= 1) ss += __shfl_xor_sync(0xffffffffu, ss, o);
    if ((threadIdx.x & 31) == 0) sh[threadIdx.x >> 5] = ss;
    __syncthreads();
    float tot = 0.f;
    #pragma unroll
    for (int i = 0; i < 8; i++) tot += sh[i];
    const float sc = rsqrtf(tot * (1.0f / DIM) + EPSV);
    #pragma unroll
    for (int i = 0; i < 8; i++) {
        int c = threadIdx.x + 256*i;
        float y = v[i] * sc * g[c];
        long o = row * (long)DIM + c;
        if (yf) yf[o] = y;
        ya[o] = __float2half(y);
    }
}

// ---------------- lambda ----------------
__global__ void lambda_kernel(const float* __restrict__ lq1, const float* __restrict__ lk1,
                              const float* __restrict__ lq2, const float* __restrict__ lk2,
                              float* __restrict__ lam) {
    __shared__ float s1[128], s2[128];
    int h = blockIdx.x, t = threadIdx.x;
    int i = h * HDIM + t;
    s1[t] = lq1[i] * lk1[i];
    s2[t] = lq2[i] * lk2[i];
    __syncthreads();
    for (int o = 64; o; o >>= 1) {
        if (t < o) { s1[t] += s1[t+o]; s2[t] += s2[t+o]; }
        __syncthreads();
    }
    if (t == 0) lam[h] = expf(s1[0]) - expf(s2[0]) + LAMB0;
}

// ---------------- launcher ----------------
extern "C" void kernel_launch(void* const* d_in, const int* in_sizes, int n_in,
                              void* d_out, int out_size) {
    (void)in_sizes; (void)n_in; (void)out_size;
    const float* x   = (const float*)d_in[0];
    const float* gn  = (const float*)d_in[1];
    const float* Wq1 = (const float*)d_in[2];
    const float* Wq2 = (const float*)d_in[3];
    const float* Wk1 = (const float*)d_in[4];
    const float* Wk2 = (const float*)d_in[5];
    const float* Wv  = (const float*)d_in[6];
    const float* lq1 = (const float*)d_in[7];
    const float* lk1 = (const float*)d_in[8];
    const float* lq2 = (const float*)d_in[9];
    const float* lk2 = (const float*)d_in[10];
    const float* Wo  = (const float*)d_in[11];
    const float* W1  = (const float*)d_in[12];
    const float* W2  = (const float*)d_in[13];
    const float* W3  = (const float*)d_in[14];
    float* out = (float*)d_out;

    const int SMEM  = 3 * 20480;         // 61440 (GEMM, 3 stages)
    const int FSMEM = 32768 + 2 * 32768; // 98304 (flash)
    cudaFuncSetAttribute(mma_gemm<0>, cudaFuncAttributeMaxDynamicSharedMemorySize, SMEM);
    cudaFuncSetAttribute(mma_gemm<2>, cudaFuncAttributeMaxDynamicSharedMemorySize, SMEM);
    cudaFuncSetAttribute(mma_gemm<3>, cudaFuncAttributeMaxDynamicSharedMemorySize, SMEM);
    cudaFuncSetAttribute(flash_branch, cudaFuncAttributeMaxDynamicSharedMemorySize, FSMEM);

#define SYM(v, s) cudaGetSymbolAddress((void**)&v, s)
    float *h0f, *hf, *lam;
    SYM(h0f, g_h0f); SYM(hf, g_hf); SYM(lam, g_lam);
    fp16 *h0a,*za,*qk,*vt,*o1,*o2,*oa,*g1h,*ua;
    fp16 *fwqkv,*fwo,*fw12,*fw3;
    SYM(h0a, g_h0a); SYM(za, g_za); SYM(qk, g_qk); SYM(vt, g_vt);
    SYM(o1, g_o1); SYM(o2, g_o2); SYM(oa, g_oa); SYM(g1h, g_g1h); SYM(ua, g_ua);
    SYM(fwqkv, g_fwqkv); SYM(fwo, g_fwo); SYM(fw12, g_fw12); SYM(fw3, g_fw3);
#undef SYM

    const long SD = (long)SEQ * DIM;
    const long DD = (long)DIM * DIM;
    fp16* q1 = qk;
    fp16* q2 = qk + SD;
    fp16* k1 = qk + 2 * SD;
    fp16* k2 = qk + 3 * SD;
    fp16* fwv = fwqkv + 4 * DD;
    fp16* fw1 = fw12;
    fp16* fw2 = fw12 + (long)DIM * HIDN;

    // ---- pre-flash: 5 launches ----
    dim3 g5(HDIM/32, DIM/32, 5 * NH);
    wt5_kernel<<<g5, 256>>>(Wq1, Wq2, Wk1, Wk2, Wv, fwqkv);
    rmsnorm_kernel<<<SEQ, 256>>>(x, gn, h0f, h0a);
    dim3 gproj(DIM/128, SEQ/128, 4);
    mma_gemm<2><<<gproj, 512, SMEM>>>(h0a, DIM, 0, fwqkv, DIM, DD, nullptr, nullptr, nullptr, qk, DIM, SD, DIM, 1.f);
    dim3 gvt(SEQ/128, DIM/128, 1);
    mma_gemm<2><<<gvt, 512, SMEM>>>(fwv, DIM, 0, h0a, DIM, 0, nullptr, nullptr, nullptr, vt, SEQ, 0, DIM, 1.f);
    dim3 gfl(SEQ/128, NH);
    flash_branch<<<gfl, 256, FSMEM>>>(q1, k1, vt, o1);
    flash_branch<<<gfl, 256, FSMEM>>>(q2, k2, vt, o2);

    lambda_kernel<<<NH, 128>>>(lq1, lk1, lq2, lk2, lam);
    combine_kernel<<<(SEQ * DIM / 2) / 256, 256>>>(o1, o2, lam, oa);

    dim3 gtO(DIM/32, DIM/32, 1);
    transpose_half2<<<gtO, 256>>>(Wo, Wo, fwo, DIM, DIM);
    dim3 gwo(DIM/128, SEQ/128, 1);
    mma_gemm<0><<<gwo, 512, SMEM>>>(oa, DIM, 0, fwo, DIM, 0, hf, h0f, nullptr, nullptr, DIM, 0, DIM, 1.f);

    rmsnorm_kernel<<<SEQ, 256>>>(hf, gn, nullptr, za);

    dim3 gt12(HIDN/32, DIM/32, 2);
    transpose_half2<<<gt12, 256>>>(W1, W2, fw12, DIM, HIDN);
    dim3 gt3(DIM/32, HIDN/32, 1);
    transpose_half2<<<gt3, 256>>>(W3, W3, fw3, HIDN, DIM);

    dim3 gffn(HIDN/128, SEQ/128, 1);
    mma_gemm<2><<<gffn, 512, SMEM>>>(za, DIM, 0, fw1, DIM, 0, nullptr, nullptr, nullptr, g1h, HIDN, 0, DIM, 1.f);
    mma_gemm<3><<<gffn, 512, SMEM>>>(za, DIM, 0, fw2, DIM, 0, nullptr, nullptr, g1h, ua, HIDN, 0, DIM, 1.f);

    dim3 gw3(DIM/128, SEQ/128, 1);
    mma_gemm<0><<<gw3, 512, SMEM>>>(ua, HIDN, 0, fw3, HIDN, 0, out, hf, nullptr, nullptr, DIM, 0, HIDN, 1.f);
}

// round 16
// speedup vs baseline: 1.1899x; 1.0121x over previous
#include <cuda_runtime.h>
#include <cuda_fp16.h>
#include <math.h>
#include <stdint.h>

#define SEQ 2048
#define DIM 2048
#define NH 16
#define HDIM 128
#define HIDN 8192
#define EPSV 1e-6f
#define LAMB0 0.8f

typedef __half fp16;

// ---------------- scratch ----------------
__device__ float g_h0f[SEQ * DIM];
__device__ float g_hf [SEQ * DIM];
__device__ float g_lam[NH];

__device__ fp16 g_h0a[SEQ*DIM];
__device__ fp16 g_za [SEQ*DIM];
__device__ fp16 g_qk [(size_t)5*SEQ*DIM];        // q1,q2,k1,k2,vr slices
__device__ fp16 g_vt [SEQ*DIM];                  // V^T [H*DH, SEQ]
__device__ fp16 g_o1 [SEQ*DIM], g_o2[SEQ*DIM];
__device__ fp16 g_oa [SEQ*DIM];
__device__ fp16 g_g1h[(size_t)SEQ*HIDN];
__device__ fp16 g_ua [(size_t)SEQ*HIDN];
__device__ fp16 g_fwqkv[(size_t)5*DIM*DIM];
__device__ fp16 g_fwo [DIM*DIM];
__device__ fp16 g_fw12[(size_t)2*DIM*HIDN];
__device__ fp16 g_fw3[(size_t)DIM*HIDN];

// ---------------- helpers ----------------
__device__ __forceinline__ uint32_t smem_u32(const void* p) {
    uint32_t a;
    asm("{ .reg .u64 t; cvta.to.shared.u64 t, %1; cvt.u32.u64 %0, t; }" : "=r"(a) : "l"(p));
    return a;
}
__device__ __forceinline__ void cpa16(uint32_t s, const void* g) {
    asm volatile("cp.async.cg.shared.global [%0], [%1], 16;" :: "r"(s), "l"(g));
}
#define CP_COMMIT() asm volatile("cp.async.commit_group;")
#define CP_WAIT(n)  asm volatile("cp.async.wait_group %0;" :: "n"(n))

__device__ __forceinline__ void ldm4(uint32_t* r, uint32_t addr) {
    asm volatile("ldmatrix.sync.aligned.m8n8.x4.shared.b16 {%0,%1,%2,%3}, [%4];"
        : "=r"(r[0]), "=r"(r[1]), "=r"(r[2]), "=r"(r[3]) : "r"(addr));
}
__device__ __forceinline__ void mma_hf(float* d, const uint32_t* a, uint32_t b0, uint32_t b1) {
    asm volatile("mma.sync.aligned.m16n8k16.row.col.f32.f16.f16.f32 "
        "{%0,%1,%2,%3}, {%4,%5,%6,%7}, {%8,%9}, {%0,%1,%2,%3};"
        : "+f"(d[0]), "+f"(d[1]), "+f"(d[2]), "+f"(d[3])
        : "r"(a[0]), "r"(a[1]), "r"(a[2]), "r"(a[3]), "r"(b0), "r"(b1));
}

// FMA-pipe exp
__device__ __forceinline__ float fexp(float x) {
    float y = x * 1.44269504089f;
    y = fmaxf(fminf(y, 126.0f), -125.0f);
    float z = __fadd_rn(y, 12582912.0f);
    float n = __fsub_rn(z, 12582912.0f);
    float f = __fsub_rn(y, n);
    float p =            1.33335581e-3f;
    p = fmaf(p, f, 9.61812911e-3f);
    p = fmaf(p, f, 5.55041087e-2f);
    p = fmaf(p, f, 2.40226507e-1f);
    p = fmaf(p, f, 6.93147181e-1f);
    p = fmaf(p, f, 1.0f);
    int i = __float_as_int(z);
    float s = __int_as_float((i << 23) + 0x3F800000);
    return p * s;
}

// ---------------- fp16 1-product GEMM (round-13 best config) ----------------
// MODE 0: fp32 (+residual Rf). MODE 2: fp16. MODE 3: fp16 = silu(Rh)*acc.
template <int MODE>
__global__ __launch_bounds__(256) void mma_gemm(
    const fp16* __restrict__ Ah, int lda, long sA,
    const fp16* __restrict__ B, int ldb, long sB,
    float* __restrict__ Cf, const float* __restrict__ Rf, const fp16* __restrict__ Rh,
    fp16* __restrict__ Ch,
    int ldc, long sC, int K, float alpha)
{
    constexpr int RSB  = 80;
    constexpr int MATB = 128 * RSB;
    constexpr int STG  = 2 * MATB;
    extern __shared__ __align__(128) char dsm[];
    const uint32_t sb = smem_u32(dsm);

    const int tid = threadIdx.x;
    const int m0 = blockIdx.y * 128, n0 = blockIdx.x * 128, z = blockIdx.z;

    Ah += (long)z * sA + (long)m0 * lda;
    B  += (long)z * sB + (long)n0 * ldb;

    const int NC = K >> 5;

    auto load_chunk = [&](int c, int s) {
        const long k0 = (long)c << 5;
        const uint32_t st = sb + (uint32_t)s * STG;
        #pragma unroll
        for (int i = 0; i < 2; i++) {
            int idx = tid + 256 * i;
            int row = idx >> 2;
            int sg  = idx & 3;
            uint32_t so = st + (uint32_t)row * RSB + (uint32_t)sg * 16;
            cpa16(so,        Ah + (long)row * lda + k0 + sg * 8);
            cpa16(so + MATB, B  + (long)row * ldb + k0 + sg * 8);
        }
    };

    const int l  = tid & 31;
    const int wp = tid >> 5;
    const int wm = (wp >> 2) * 64;
    const int wn = (wp & 3) * 32;
    const uint32_t aoff = (uint32_t)(wm + (l & 15)) * RSB + (uint32_t)((l >> 4) * 16);
    const uint32_t boff = (uint32_t)MATB + (uint32_t)(wn + (l & 7) + ((l >> 4) << 3)) * RSB
                        + (uint32_t)(((l >> 3) & 1) * 16);

    float acc[4][4][4];
    #pragma unroll
    for (int a = 0; a < 4; a++)
        #pragma unroll
        for (int b = 0; b < 4; b++)
            #pragma unroll
            for (int c = 0; c < 4; c++) acc[a][b][c] = 0.f;

    load_chunk(0, 0); CP_COMMIT();
    load_chunk(1, 1); CP_COMMIT();
    load_chunk(2, 2); CP_COMMIT();

    for (int c = 0; c < NC; c++) {
        const int s = c & 3;
        const int rem = NC - 1 - c;
        if (rem >= 2)      { CP_WAIT(2); }
        else if (rem == 1) { CP_WAIT(1); }
        else               { CP_WAIT(0); }
        __syncthreads();
        if (c + 3 < NC) { load_chunk(c + 3, (c + 3) & 3); CP_COMMIT(); }

        const uint32_t stg = sb + (uint32_t)s * STG;
        #pragma unroll
        for (int ks = 0; ks < 2; ks++) {
            const uint32_t base = stg + (uint32_t)ks * 32;
            uint32_t ah[4][4], bh[2][4];
            #pragma unroll
            for (int mi = 0; mi < 4; mi++)
                ldm4(ah[mi], base + aoff + (uint32_t)mi * (16 * RSB));
            #pragma unroll
            for (int ng = 0; ng < 2; ng++)
                ldm4(bh[ng], base + boff + (uint32_t)ng * (16 * RSB));
            #pragma unroll
            for (int mi = 0; mi < 4; mi++)
                #pragma unroll
                for (int ni = 0; ni < 4; ni++)
                    mma_hf(acc[mi][ni], ah[mi],
                           bh[ni >> 1][(ni & 1) * 2], bh[ni >> 1][(ni & 1) * 2 + 1]);
        }
    }

    const int qr = l >> 2;
    const int qc = (l & 3) * 2;
    const long cbase = (long)z * sC + (long)m0 * ldc + n0;
    #pragma unroll
    for (int mi = 0; mi < 4; mi++)
        #pragma unroll
        for (int ni = 0; ni < 4; ni++)
            #pragma unroll
            for (int hr = 0; hr < 2; hr++) {
                long off = cbase + (long)(wm + mi * 16 + qr + hr * 8) * ldc + (wn + ni * 8 + qc);
                float v0 = acc[mi][ni][hr * 2 + 0] * alpha;
                float v1 = acc[mi][ni][hr * 2 + 1] * alpha;
                if (MODE == 0) {
                    if (Rf) { v0 += Rf[off]; v1 += Rf[off + 1]; }
                    Cf[off] = v0; Cf[off + 1] = v1;
                } else if (MODE == 2) {
                    Ch[off]     = __float2half(v0);
                    Ch[off + 1] = __float2half(v1);
                } else {
                    float a0 = __half2float(Rh[off]),     s0 = a0 / (1.f + fexp(-a0));
                    float a1 = __half2float(Rh[off + 1]), s1 = a1 / (1.f + fexp(-a1));
                    Ch[off]     = __float2half(s0 * v0);
                    Ch[off + 1] = __float2half(s1 * v1);
                }
            }
}

// ---------------- both flash branches in one launch (z = branch) ----------------
__global__ __launch_bounds__(256, 1) void flash_both(
    const fp16* __restrict__ q1, const fp16* __restrict__ q2,
    const fp16* __restrict__ k1, const fp16* __restrict__ k2,
    const fp16* __restrict__ vtg,
    fp16* __restrict__ o1, fp16* __restrict__ o2)
{
    extern __shared__ __align__(128) char dsm[];
    const uint32_t sb = smem_u32(dsm);
    const int tid = threadIdx.x;
    const int l = tid & 31, w = tid >> 5;
    const int m0 = blockIdx.x * 128;
    const int h  = blockIdx.y;
    const int bz = blockIdx.z;
    const fp16* qg = bz ? q2 : q1;
    const fp16* kg = bz ? k2 : k1;
    fp16* ob = bz ? o2 : o1;

    {
        const fp16* gq = qg + (long)m0 * DIM + h * HDIM;
        #pragma unroll
        for (int i = 0; i < 8; i++) {
            int idx = tid + i * 256;
            int row = idx >> 4, j = idx & 15;
            cpa16(sb + (uint32_t)row * 256 + (uint32_t)((j ^ (row & 7)) << 4),
                  gq + (long)row * DIM + j * 8);
        }
    }

    auto load_stage = [&](int kt, int s) {
        const uint32_t st = sb + 32768 + (uint32_t)s * 32768;
        const int kb = kt * 64;
        const fp16* gk = kg + (long)kb * DIM + h * HDIM;
        #pragma unroll
        for (int i = 0; i < 4; i++) {
            int idx = tid + i * 256;
            int row = idx >> 4, j = idx & 15;
            cpa16(st + (uint32_t)row * 256 + (uint32_t)((j ^ (row & 7)) << 4),
                  gk + (long)row * DIM + j * 8);
        }
        const fp16* gv = vtg + (long)(h * HDIM) * SEQ + kb;
        #pragma unroll
        for (int i = 0; i < 4; i++) {
            int idx = tid + i * 256;
            int row = idx >> 3, j = idx & 7;
            cpa16(st + 16384 + (uint32_t)row * 128 + (uint32_t)((j ^ (row & 7)) << 4),
                  gv + (long)row * SEQ + j * 8);
        }
    };
    load_stage(0, 0); CP_COMMIT();
    load_stage(1, 1); CP_COMMIT();

    const int arow = w * 16 + (l & 15);
    const int axor = arow & 7;
    const int alo  = l >> 4;
    const uint32_t aQ = sb + (uint32_t)arow * 256;
    const int bn  = (l & 7) + ((l >> 4) << 3);
    const int bko = (l >> 3) & 1;
    const int bxor = bn & 7;

    float m0s = -1e30f, m1s = -1e30f, l0s = 0.f, l1s = 0.f;
    float O[16][4];
    #pragma unroll
    for (int d = 0; d < 16; d++)
        #pragma unroll
        for (int e = 0; e < 4; e++) O[d][e] = 0.f;

    const float qksc = 0.08838834764831845f;

    #pragma unroll 1
    for (int kt = 0; kt < 32; kt++) {
        CP_WAIT(1);
        __syncthreads();
        const uint32_t st = sb + 32768 + (uint32_t)(kt & 1) * 32768;

        float sa[8][4];
        #pragma unroll
        for (int i = 0; i < 8; i++)
            #pragma unroll
            for (int e = 0; e < 4; e++) sa[i][e] = 0.f;
        {
            uint32_t qa[8][4];
            #pragma unroll
            for (int t = 0; t < 8; t++)
                ldm4(qa[t], aQ + (uint32_t)(((2*t + alo) ^ axor) << 4));
            #pragma unroll
            for (int ng = 0; ng < 4; ng++) {
                const uint32_t krow = st + (uint32_t)(ng*16 + bn) * 256;
                #pragma unroll
                for (int t = 0; t < 8; t++) {
                    uint32_t bf[4];
                    ldm4(bf, krow + (uint32_t)(((2*t + bko) ^ bxor) << 4));
                    mma_hf(sa[2*ng],   qa[t], bf[0], bf[1]);
                    mma_hf(sa[2*ng+1], qa[t], bf[2], bf[3]);
                }
            }
        }

        float rm0 = -1e30f, rm1 = -1e30f;
        #pragma unroll
        for (int i = 0; i < 8; i++) {
            #pragma unroll
            for (int e = 0; e < 4; e++) sa[i][e] *= qksc;
            rm0 = fmaxf(rm0, fmaxf(sa[i][0], sa[i][1]));
            rm1 = fmaxf(rm1, fmaxf(sa[i][2], sa[i][3]));
        }
        rm0 = fmaxf(rm0, __shfl_xor_sync(0xffffffffu, rm0, 1));
        rm0 = fmaxf(rm0, __shfl_xor_sync(0xffffffffu, rm0, 2));
        rm1 = fmaxf(rm1, __shfl_xor_sync(0xffffffffu, rm1, 1));
        rm1 = fmaxf(rm1, __shfl_xor_sync(0xffffffffu, rm1, 2));
        const float mn0 = fmaxf(m0s, rm0), mn1 = fmaxf(m1s, rm1);
        const float c0 = fexp(m0s - mn0), c1 = fexp(m1s - mn1);
        #pragma unroll
        for (int d = 0; d < 16; d++) {
            O[d][0] *= c0; O[d][1] *= c0;
            O[d][2] *= c1; O[d][3] *= c1;
        }
        float ps0 = 0.f, ps1 = 0.f;
        #pragma unroll
        for (int i = 0; i < 8; i++) {
            sa[i][0] = fexp(sa[i][0] - mn0); ps0 += sa[i][0];
            sa[i][1] = fexp(sa[i][1] - mn0); ps0 += sa[i][1];
            sa[i][2] = fexp(sa[i][2] - mn1); ps1 += sa[i][2];
            sa[i][3] = fexp(sa[i][3] - mn1); ps1 += sa[i][3];
        }
        ps0 += __shfl_xor_sync(0xffffffffu, ps0, 1);
        ps0 += __shfl_xor_sync(0xffffffffu, ps0, 2);
        ps1 += __shfl_xor_sync(0xffffffffu, ps1, 1);
        ps1 += __shfl_xor_sync(0xffffffffu, ps1, 2);
        l0s = l0s * c0 + ps0;  m0s = mn0;
        l1s = l1s * c1 + ps1;  m1s = mn1;

        uint32_t pf[4][4];
        #pragma unroll
        for (int t = 0; t < 4; t++) {
            __half2 h0 = __floats2half2_rn(sa[2*t][0],   sa[2*t][1]);
            __half2 h1 = __floats2half2_rn(sa[2*t][2],   sa[2*t][3]);
            __half2 h2 = __floats2half2_rn(sa[2*t+1][0], sa[2*t+1][1]);
            __half2 h3 = __floats2half2_rn(sa[2*t+1][2], sa[2*t+1][3]);
            pf[t][0] = *(uint32_t*)&h0; pf[t][1] = *(uint32_t*)&h1;
            pf[t][2] = *(uint32_t*)&h2; pf[t][3] = *(uint32_t*)&h3;
        }

        const uint32_t vst = st + 16384;
        #pragma unroll
        for (int dg = 0; dg < 8; dg++) {
            const uint32_t vrow = vst + (uint32_t)(dg*16 + bn) * 128;
            #pragma unroll
            for (int t = 0; t < 4; t++) {
                uint32_t bf[4];
                ldm4(bf, vrow + (uint32_t)(((2*t + bko) ^ bxor) << 4));
                mma_hf(O[2*dg],   pf[t], bf[0], bf[1]);
                mma_hf(O[2*dg+1], pf[t], bf[2], bf[3]);
            }
        }
        __syncthreads();
        if (kt + 2 < 32) load_stage(kt + 2, kt & 1);
        CP_COMMIT();
    }

    const float i0 = 1.f / l0s, i1 = 1.f / l1s;
    const int r0 = m0 + w * 16 + (l >> 2);
    #pragma unroll
    for (int d = 0; d < 16; d++) {
        const int col = h * HDIM + d * 8 + 2 * (l & 3);
        __half2 p0 = __floats2half2_rn(O[d][0] * i0, O[d][1] * i0);
        __half2 p1 = __floats2half2_rn(O[d][2] * i1, O[d][3] * i1);
        *(uint32_t*)&ob[(long)r0 * DIM + col]       = *(uint32_t*)&p0;
        *(uint32_t*)&ob[(long)(r0 + 8) * DIM + col] = *(uint32_t*)&p1;
    }
}

// ---------------- combine ----------------
__global__ __launch_bounds__(256) void combine_kernel(
    const fp16* __restrict__ o1, const fp16* __restrict__ o2,
    const float* __restrict__ lam, fp16* __restrict__ oa)
{
    long i = (long)blockIdx.x * 256 + threadIdx.x;
    int h = (int)((i * 2) % DIM) / HDIM;
    float lm = lam[h];
    __half2 a = ((const __half2*)o1)[i];
    __half2 b = ((const __half2*)o2)[i];
    float2 af = __half22float2(a), bf = __half22float2(b);
    __half2 r = __floats2half2_rn(af.x - lm * bf.x, af.y - lm * bf.y);
    ((__half2*)oa)[i] = r;
}

// ---------------- batched QKV weight transpose ----------------
__global__ __launch_bounds__(256) void wt5_kernel(
    const float* __restrict__ w0, const float* __restrict__ w1,
    const float* __restrict__ w2, const float* __restrict__ w3,
    const float* __restrict__ w4, fp16* __restrict__ outb)
{
    const int z = blockIdx.z;
    const int m = z >> 4, h = z & 15;
    const float* in = (m == 0 ? w0 : m == 1 ? w1 : m == 2 ? w2 : m == 3 ? w3 : w4)
                    + (long)h * DIM * HDIM;
    fp16* oh = outb + (long)m * DIM * DIM + (long)h * HDIM * DIM;
    const int c0 = blockIdx.x * 32, r0 = blockIdx.y * 32;
    __shared__ float t[32][33];
    const int tx = threadIdx.x & 31, ty = threadIdx.x >> 5;
    #pragma unroll
    for (int i = 0; i < 4; i++)
        t[ty + 8*i][tx] = in[(long)(r0 + ty + 8*i) * HDIM + c0 + tx];
    __syncthreads();
    #pragma unroll
    for (int i = 0; i < 4; i++)
        oh[(long)(c0 + ty + 8*i) * DIM + r0 + tx] = __float2half(t[tx][ty + 8*i]);
}

// ---------------- fp16 -> fp16 transpose ----------------
__global__ __launch_bounds__(256) void transpose_hh(const fp16* __restrict__ in,
                                                    fp16* __restrict__ oh,
                                                    int R, int C) {
    const int c0 = blockIdx.x * 32, r0 = blockIdx.y * 32;
    __shared__ fp16 t[32][34];
    const int tx = threadIdx.x & 31, ty = threadIdx.x >> 5;
    #pragma unroll
    for (int i = 0; i < 4; i++)
        t[ty + 8*i][tx] = in[(long)(r0 + ty + 8*i) * C + c0 + tx];
    __syncthreads();
    #pragma unroll
    for (int i = 0; i < 4; i++)
        oh[(long)(c0 + ty + 8*i) * R + r0 + tx] = t[tx][ty + 8*i];
}

// ---------------- generic transpose fp32->fp16 ----------------
__global__ __launch_bounds__(256) void transpose_half2(
    const float* __restrict__ inA, const float* __restrict__ inB,
    fp16* __restrict__ outb, int R, int C)
{
    const int z = blockIdx.z;
    const float* in = (z == 0) ? inA : inB;
    fp16* oh = outb + (long)z * R * C;
    const int c0 = blockIdx.x * 32, r0 = blockIdx.y * 32;
    __shared__ float t[32][33];
    const int tx = threadIdx.x & 31, ty = threadIdx.x >> 5;
    #pragma unroll
    for (int i = 0; i < 4; i++)
        t[ty + 8*i][tx] = in[(long)(r0 + ty + 8*i) * C + c0 + tx];
    __syncthreads();
    #pragma unroll
    for (int i = 0; i < 4; i++)
        oh[(long)(c0 + ty + 8*i) * R + r0 + tx] = __float2half(t[tx][ty + 8*i]);
}

// ---------------- RMSNorm ----------------
__global__ __launch_bounds__(256) void rmsnorm_kernel(const float* __restrict__ x,
                                                      const float* __restrict__ g,
                                                      float* __restrict__ yf,
                                                      fp16* __restrict__ ya) {
    __shared__ float sh[8];
    const long row = blockIdx.x;
    const float* xr = x + row * (long)DIM;
    float v[8], ss = 0.f;
    #pragma unroll
    for (int i = 0; i < 8; i++) { v[i] = xr[threadIdx.x + 256*i]; ss += v[i]*v[i]; }
    #pragma unroll
    for (int o = 16; o; o >>= 1) ss += __shfl_xor_sync(0xffffffffu, ss, o);
    if ((threadIdx.x & 31) == 0) sh[threadIdx.x >> 5] = ss;
    __syncthreads();
    float tot = 0.f;
    #pragma unroll
    for (int i = 0; i < 8; i++) tot += sh[i];
    const float sc = rsqrtf(tot * (1.0f / DIM) + EPSV);
    #pragma unroll
    for (int i = 0; i < 8; i++) {
        int c = threadIdx.x + 256*i;
        float y = v[i] * sc * g[c];
        long o = row * (long)DIM + c;
        if (yf) yf[o] = y;
        ya[o] = __float2half(y);
    }
}

// ---------------- lambda ----------------
__global__ void lambda_kernel(const float* __restrict__ lq1, const float* __restrict__ lk1,
                              const float* __restrict__ lq2, const float* __restrict__ lk2,
                              float* __restrict__ lam) {
    __shared__ float s1[128], s2[128];
    int h = blockIdx.x, t = threadIdx.x;
    int i = h * HDIM + t;
    s1[t] = lq1[i] * lk1[i];
    s2[t] = lq2[i] * lk2[i];
    __syncthreads();
    for (int o = 64; o; o >>= 1) {
        if (t < o) { s1[t] += s1[t+o]; s2[t] += s2[t+o]; }
        __syncthreads();
    }
    if (t == 0) lam[h] = expf(s1[0]) - expf(s2[0]) + LAMB0;
}

// ---------------- launcher ----------------
extern "C" void kernel_launch(void* const* d_in, const int* in_sizes, int n_in,
                              void* d_out, int out_size) {
    (void)in_sizes; (void)n_in; (void)out_size;
    const float* x   = (const float*)d_in[0];
    const float* gn  = (const float*)d_in[1];
    const float* Wq1 = (const float*)d_in[2];
    const float* Wq2 = (const float*)d_in[3];
    const float* Wk1 = (const float*)d_in[4];
    const float* Wk2 = (const float*)d_in[5];
    const float* Wv  = (const float*)d_in[6];
    const float* lq1 = (const float*)d_in[7];
    const float* lk1 = (const float*)d_in[8];
    const float* lq2 = (const float*)d_in[9];
    const float* lk2 = (const float*)d_in[10];
    const float* Wo  = (const float*)d_in[11];
    const float* W1  = (const float*)d_in[12];
    const float* W2  = (const float*)d_in[13];
    const float* W3  = (const float*)d_in[14];
    float* out = (float*)d_out;

    const int SMEM  = 4 * 2 * 10240;     // 81920 (GEMM)
    const int FSMEM = 32768 + 2 * 32768; // 98304 (flash)
    cudaFuncSetAttribute(mma_gemm<0>, cudaFuncAttributeMaxDynamicSharedMemorySize, SMEM);
    cudaFuncSetAttribute(mma_gemm<2>, cudaFuncAttributeMaxDynamicSharedMemorySize, SMEM);
    cudaFuncSetAttribute(mma_gemm<3>, cudaFuncAttributeMaxDynamicSharedMemorySize, SMEM);
    cudaFuncSetAttribute(flash_both, cudaFuncAttributeMaxDynamicSharedMemorySize, FSMEM);

#define SYM(v, s) cudaGetSymbolAddress((void**)&v, s)
    float *h0f, *hf, *lam;
    SYM(h0f, g_h0f); SYM(hf, g_hf); SYM(lam, g_lam);
    fp16 *h0a,*za,*qk,*vt,*o1,*o2,*oa,*g1h,*ua;
    fp16 *fwqkv,*fwo,*fw12,*fw3;
    SYM(h0a, g_h0a); SYM(za, g_za); SYM(qk, g_qk); SYM(vt, g_vt);
    SYM(o1, g_o1); SYM(o2, g_o2); SYM(oa, g_oa); SYM(g1h, g_g1h); SYM(ua, g_ua);
    SYM(fwqkv, g_fwqkv); SYM(fwo, g_fwo); SYM(fw12, g_fw12); SYM(fw3, g_fw3);
#undef SYM

    const long SD = (long)SEQ * DIM;
    const long DD = (long)DIM * DIM;
    fp16* q1 = qk;
    fp16* q2 = qk + SD;
    fp16* k1 = qk + 2 * SD;
    fp16* k2 = qk + 3 * SD;
    fp16* vr = qk + 4 * SD;
    fp16* fw1 = fw12;
    fp16* fw2 = fw12 + (long)DIM * HIDN;

    // 1) batched QKV weight transpose
    dim3 g5(HDIM/32, DIM/32, 5 * NH);
    wt5_kernel<<<g5, 256>>>(Wq1, Wq2, Wk1, Wk2, Wv, fwqkv);
    // 2) h0 = rmsnorm(x)
    rmsnorm_kernel<<<SEQ, 256>>>(x, gn, h0f, h0a);
    // 3) lambda (early so flash is launch #6 for ncu)
    lambda_kernel<<<NH, 128>>>(lq1, lk1, lq2, lk2, lam);
    // 4) q1,q2,k1,k2,V batched projection (z = 5; z=4 -> V row-major)
    dim3 gproj(DIM/128, SEQ/128, 5);
    mma_gemm<2><<<gproj, 256, SMEM>>>(h0a, DIM, 0, fwqkv, DIM, DD, nullptr, nullptr, nullptr, qk, DIM, SD, DIM, 1.f);
    // 5) V^T (fp16->fp16)
    dim3 gtV(DIM/32, SEQ/32, 1);
    transpose_hh<<<gtV, 256>>>(vr, vt, SEQ, DIM);
    // 6) both flash branches, one launch (512 CTAs)
    dim3 gfl(SEQ/128, NH, 2);
    flash_both<<<gfl, 256, FSMEM>>>(q1, q2, k1, k2, vt, o1, o2);

    // combine
    combine_kernel<<<(SEQ * DIM / 2) / 256, 256>>>(o1, o2, lam, oa);

    // Wo transpose + h = O @ Wo + h0
    dim3 gtO(DIM/32, DIM/32, 1);
    transpose_half2<<<gtO, 256>>>(Wo, Wo, fwo, DIM, DIM);
    dim3 gwo(DIM/128, SEQ/128, 1);
    mma_gemm<0><<<gwo, 256, SMEM>>>(oa, DIM, 0, fwo, DIM, 0, hf, h0f, nullptr, nullptr, DIM, 0, DIM, 1.f);

    // z = rmsnorm(h)
    rmsnorm_kernel<<<SEQ, 256>>>(hf, gn, nullptr, za);

    // FFN weight transposes + GEMMs
    dim3 gt12(HIDN/32, DIM/32, 2);
    transpose_half2<<<gt12, 256>>>(W1, W2, fw12, DIM, HIDN);
    dim3 gt3(DIM/32, HIDN/32, 1);
    transpose_half2<<<gt3, 256>>>(W3, W3, fw3, HIDN, DIM);

    dim3 gffn(HIDN/128, SEQ/128, 1);
    mma_gemm<2><<<gffn, 256, SMEM>>>(za, DIM, 0, fw1, DIM, 0, nullptr, nullptr, nullptr, g1h, HIDN, 0, DIM, 1.f);
    mma_gemm<3><<<gffn, 256, SMEM>>>(za, DIM, 0, fw2, DIM, 0, nullptr, nullptr, g1h, ua, HIDN, 0, DIM, 1.f);

    dim3 gw3(DIM/128, SEQ/128, 1);
    mma_gemm<0><<<gw3, 256, SMEM>>>(ua, HIDN, 0, fw3, HIDN, 0, out, hf, nullptr, nullptr, DIM, 0, HIDN, 1.f);
}

// round 17
// speedup vs baseline: 1.2890x; 1.0833x over previous
#include <cuda_runtime.h>
#include <cuda_fp16.h>
#include <math.h>
#include <stdint.h>

#define SEQ 2048
#define DIM 2048
#define NH 16
#define HDIM 128
#define HIDN 8192
#define EPSV 1e-6f
#define LAMB0 0.8f

typedef __half fp16;

// ---------------- scratch ----------------
__device__ float g_h0f[SEQ * DIM];
__device__ float g_hf [SEQ * DIM];
__device__ float g_lam[NH];

__device__ fp16 g_h0a[SEQ*DIM];
__device__ fp16 g_za [SEQ*DIM];
__device__ fp16 g_qk [(size_t)5*SEQ*DIM];        // q1,q2,k1,k2,vr slices
__device__ fp16 g_vt [SEQ*DIM];                  // V^T [H*DH, SEQ]
__device__ fp16 g_o1 [SEQ*DIM], g_o2[SEQ*DIM];
__device__ fp16 g_oa [SEQ*DIM];
__device__ fp16 g_g1h[(size_t)SEQ*HIDN];
__device__ fp16 g_ua [(size_t)SEQ*HIDN];
__device__ fp16 g_fwqkv[(size_t)5*DIM*DIM];
__device__ fp16 g_fwo [DIM*DIM];
__device__ fp16 g_fw12[(size_t)2*DIM*HIDN];
__device__ fp16 g_fw3[(size_t)DIM*HIDN];

// ---------------- helpers ----------------
__device__ __forceinline__ uint32_t smem_u32(const void* p) {
    uint32_t a;
    asm("{ .reg .u64 t; cvta.to.shared.u64 t, %1; cvt.u32.u64 %0, t; }" : "=r"(a) : "l"(p));
    return a;
}
__device__ __forceinline__ void cpa16(uint32_t s, const void* g) {
    asm volatile("cp.async.cg.shared.global [%0], [%1], 16;" :: "r"(s), "l"(g));
}
#define CP_COMMIT() asm volatile("cp.async.commit_group;")
#define CP_WAIT(n)  asm volatile("cp.async.wait_group %0;" :: "n"(n))

__device__ __forceinline__ void ldm4(uint32_t* r, uint32_t addr) {
    asm volatile("ldmatrix.sync.aligned.m8n8.x4.shared.b16 {%0,%1,%2,%3}, [%4];"
        : "=r"(r[0]), "=r"(r[1]), "=r"(r[2]), "=r"(r[3]) : "r"(addr));
}
__device__ __forceinline__ void mma_hf(float* d, const uint32_t* a, uint32_t b0, uint32_t b1) {
    asm volatile("mma.sync.aligned.m16n8k16.row.col.f32.f16.f16.f32 "
        "{%0,%1,%2,%3}, {%4,%5,%6,%7}, {%8,%9}, {%0,%1,%2,%3};"
        : "+f"(d[0]), "+f"(d[1]), "+f"(d[2]), "+f"(d[3])
        : "r"(a[0]), "r"(a[1]), "r"(a[2]), "r"(a[3]), "r"(b0), "r"(b1));
}

// FMA-pipe exp
__device__ __forceinline__ float fexp(float x) {
    float y = x * 1.44269504089f;
    y = fmaxf(fminf(y, 126.0f), -125.0f);
    float z = __fadd_rn(y, 12582912.0f);
    float n = __fsub_rn(z, 12582912.0f);
    float f = __fsub_rn(y, n);
    float p =            1.33335581e-3f;
    p = fmaf(p, f, 9.61812911e-3f);
    p = fmaf(p, f, 5.55041087e-2f);
    p = fmaf(p, f, 2.40226507e-1f);
    p = fmaf(p, f, 6.93147181e-1f);
    p = fmaf(p, f, 1.0f);
    int i = __float_as_int(z);
    float s = __int_as_float((i << 23) + 0x3F800000);
    return p * s;
}

// ---------------- fp16 1-product GEMM: KC=64, 3-stage ring ----------------
// Tile 128x128, 8 warps of 64x32. RSB=144 (128B data + 16B pad: ldmatrix
// 8-row phases land at 0,16,...,112 mod 128 -> conflict-free).
// MODE 0: fp32 (+residual Rf). MODE 2: fp16. MODE 3: fp16 = silu(Rh)*acc.
template <int MODE>
__global__ __launch_bounds__(256) void mma_gemm(
    const fp16* __restrict__ Ah, int lda, long sA,
    const fp16* __restrict__ B, int ldb, long sB,
    float* __restrict__ Cf, const float* __restrict__ Rf, const fp16* __restrict__ Rh,
    fp16* __restrict__ Ch,
    int ldc, long sC, int K, float alpha)
{
    constexpr int RSB  = 144;               // 64 fp16 (128B) + 16B pad
    constexpr int MATB = 128 * RSB;         // 18432
    constexpr int STG  = 2 * MATB;          // 36864 (A + B)
    extern __shared__ __align__(128) char dsm[];
    const uint32_t sb = smem_u32(dsm);

    const int tid = threadIdx.x;
    const int m0 = blockIdx.y * 128, n0 = blockIdx.x * 128, z = blockIdx.z;

    Ah += (long)z * sA + (long)m0 * lda;
    B  += (long)z * sB + (long)n0 * ldb;

    const int NC = K >> 6;   // KC = 64

    auto load_chunk = [&](int c, int s) {
        const long k0 = (long)c << 6;
        const uint32_t st = sb + (uint32_t)s * STG;
        #pragma unroll
        for (int i = 0; i < 8; i++) {
            int idx = tid + 256 * i;        // 0..2047
            int row = idx >> 3;             // 0..255
            int sg  = idx & 7;              // 16B segment (8 per row)
            uint32_t so = st + (uint32_t)row * RSB + (uint32_t)sg * 16;
            if (row < 128) cpa16(so, Ah + (long)row * lda + k0 + sg * 8);
            else           cpa16(so, B + (long)(row - 128) * ldb + k0 + sg * 8);
        }
    };

    const int l  = tid & 31;
    const int wp = tid >> 5;
    const int wm = (wp >> 2) * 64;
    const int wn = (wp & 3) * 32;
    const uint32_t aoff = (uint32_t)(wm + (l & 15)) * RSB + (uint32_t)((l >> 4) * 16);
    const uint32_t boff = (uint32_t)MATB + (uint32_t)(wn + (l & 7) + ((l >> 4) << 3)) * RSB
                        + (uint32_t)(((l >> 3) & 1) * 16);

    float acc[4][4][4];
    #pragma unroll
    for (int a = 0; a < 4; a++)
        #pragma unroll
        for (int b = 0; b < 4; b++)
            #pragma unroll
            for (int c = 0; c < 4; c++) acc[a][b][c] = 0.f;

    load_chunk(0, 0); CP_COMMIT();
    load_chunk(1, 1); CP_COMMIT();

    for (int c = 0; c < NC; c++) {
        if (c + 1 < NC) { CP_WAIT(1); }
        else            { CP_WAIT(0); }
        __syncthreads();
        if (c + 2 < NC) { load_chunk(c + 2, (c + 2) % 3); CP_COMMIT(); }

        const uint32_t stg = sb + (uint32_t)(c % 3) * STG;
        #pragma unroll
        for (int ks = 0; ks < 4; ks++) {
            const uint32_t base = stg + (uint32_t)ks * 32;
            uint32_t ah[4][4], bh[2][4];
            #pragma unroll
            for (int mi = 0; mi < 4; mi++)
                ldm4(ah[mi], base + aoff + (uint32_t)mi * (16 * RSB));
            #pragma unroll
            for (int ng = 0; ng < 2; ng++)
                ldm4(bh[ng], base + boff + (uint32_t)ng * (16 * RSB));
            #pragma unroll
            for (int mi = 0; mi < 4; mi++)
                #pragma unroll
                for (int ni = 0; ni < 4; ni++)
                    mma_hf(acc[mi][ni], ah[mi],
                           bh[ni >> 1][(ni & 1) * 2], bh[ni >> 1][(ni & 1) * 2 + 1]);
        }
    }

    const int qr = l >> 2;
    const int qc = (l & 3) * 2;
    const long cbase = (long)z * sC + (long)m0 * ldc + n0;
    #pragma unroll
    for (int mi = 0; mi < 4; mi++)
        #pragma unroll
        for (int ni = 0; ni < 4; ni++)
            #pragma unroll
            for (int hr = 0; hr < 2; hr++) {
                long off = cbase + (long)(wm + mi * 16 + qr + hr * 8) * ldc + (wn + ni * 8 + qc);
                float v0 = acc[mi][ni][hr * 2 + 0] * alpha;
                float v1 = acc[mi][ni][hr * 2 + 1] * alpha;
                if (MODE == 0) {
                    if (Rf) { v0 += Rf[off]; v1 += Rf[off + 1]; }
                    Cf[off] = v0; Cf[off + 1] = v1;
                } else if (MODE == 2) {
                    Ch[off]     = __float2half(v0);
                    Ch[off + 1] = __float2half(v1);
                } else {
                    float a0 = __half2float(Rh[off]),     s0 = a0 / (1.f + fexp(-a0));
                    float a1 = __half2float(Rh[off + 1]), s1 = a1 / (1.f + fexp(-a1));
                    Ch[off]     = __float2half(s0 * v0);
                    Ch[off + 1] = __float2half(s1 * v1);
                }
            }
}

// ---------------- both flash branches in one launch (z = branch) ----------------
__global__ __launch_bounds__(256, 1) void flash_both(
    const fp16* __restrict__ q1, const fp16* __restrict__ q2,
    const fp16* __restrict__ k1, const fp16* __restrict__ k2,
    const fp16* __restrict__ vtg,
    fp16* __restrict__ o1, fp16* __restrict__ o2)
{
    extern __shared__ __align__(128) char dsm[];
    const uint32_t sb = smem_u32(dsm);
    const int tid = threadIdx.x;
    const int l = tid & 31, w = tid >> 5;
    const int m0 = blockIdx.x * 128;
    const int h  = blockIdx.y;
    const int bz = blockIdx.z;
    const fp16* qg = bz ? q2 : q1;
    const fp16* kg = bz ? k2 : k1;
    fp16* ob = bz ? o2 : o1;

    {
        const fp16* gq = qg + (long)m0 * DIM + h * HDIM;
        #pragma unroll
        for (int i = 0; i < 8; i++) {
            int idx = tid + i * 256;
            int row = idx >> 4, j = idx & 15;
            cpa16(sb + (uint32_t)row * 256 + (uint32_t)((j ^ (row & 7)) << 4),
                  gq + (long)row * DIM + j * 8);
        }
    }

    auto load_stage = [&](int kt, int s) {
        const uint32_t st = sb + 32768 + (uint32_t)s * 32768;
        const int kb = kt * 64;
        const fp16* gk = kg + (long)kb * DIM + h * HDIM;
        #pragma unroll
        for (int i = 0; i < 4; i++) {
            int idx = tid + i * 256;
            int row = idx >> 4, j = idx & 15;
            cpa16(st + (uint32_t)row * 256 + (uint32_t)((j ^ (row & 7)) << 4),
                  gk + (long)row * DIM + j * 8);
        }
        const fp16* gv = vtg + (long)(h * HDIM) * SEQ + kb;
        #pragma unroll
        for (int i = 0; i < 4; i++) {
            int idx = tid + i * 256;
            int row = idx >> 3, j = idx & 7;
            cpa16(st + 16384 + (uint32_t)row * 128 + (uint32_t)((j ^ (row & 7)) << 4),
                  gv + (long)row * SEQ + j * 8);
        }
    };
    load_stage(0, 0); CP_COMMIT();
    load_stage(1, 1); CP_COMMIT();

    const int arow = w * 16 + (l & 15);
    const int axor = arow & 7;
    const int alo  = l >> 4;
    const uint32_t aQ = sb + (uint32_t)arow * 256;
    const int bn  = (l & 7) + ((l >> 4) << 3);
    const int bko = (l >> 3) & 1;
    const int bxor = bn & 7;

    float m0s = -1e30f, m1s = -1e30f, l0s = 0.f, l1s = 0.f;
    float O[16][4];
    #pragma unroll
    for (int d = 0; d < 16; d++)
        #pragma unroll
        for (int e = 0; e < 4; e++) O[d][e] = 0.f;

    const float qksc = 0.08838834764831845f;

    #pragma unroll 1
    for (int kt = 0; kt < 32; kt++) {
        CP_WAIT(1);
        __syncthreads();
        const uint32_t st = sb + 32768 + (uint32_t)(kt & 1) * 32768;

        float sa[8][4];
        #pragma unroll
        for (int i = 0; i < 8; i++)
            #pragma unroll
            for (int e = 0; e < 4; e++) sa[i][e] = 0.f;
        {
            uint32_t qa[8][4];
            #pragma unroll
            for (int t = 0; t < 8; t++)
                ldm4(qa[t], aQ + (uint32_t)(((2*t + alo) ^ axor) << 4));
            #pragma unroll
            for (int ng = 0; ng < 4; ng++) {
                const uint32_t krow = st + (uint32_t)(ng*16 + bn) * 256;
                #pragma unroll
                for (int t = 0; t < 8; t++) {
                    uint32_t bf[4];
                    ldm4(bf, krow + (uint32_t)(((2*t + bko) ^ bxor) << 4));
                    mma_hf(sa[2*ng],   qa[t], bf[0], bf[1]);
                    mma_hf(sa[2*ng+1], qa[t], bf[2], bf[3]);
                }
            }
        }

        float rm0 = -1e30f, rm1 = -1e30f;
        #pragma unroll
        for (int i = 0; i < 8; i++) {
            #pragma unroll
            for (int e = 0; e < 4; e++) sa[i][e] *= qksc;
            rm0 = fmaxf(rm0, fmaxf(sa[i][0], sa[i][1]));
            rm1 = fmaxf(rm1, fmaxf(sa[i][2], sa[i][3]));
        }
        rm0 = fmaxf(rm0, __shfl_xor_sync(0xffffffffu, rm0, 1));
        rm0 = fmaxf(rm0, __shfl_xor_sync(0xffffffffu, rm0, 2));
        rm1 = fmaxf(rm1, __shfl_xor_sync(0xffffffffu, rm1, 1));
        rm1 = fmaxf(rm1, __shfl_xor_sync(0xffffffffu, rm1, 2));
        const float mn0 = fmaxf(m0s, rm0), mn1 = fmaxf(m1s, rm1);
        const float c0 = fexp(m0s - mn0), c1 = fexp(m1s - mn1);
        #pragma unroll
        for (int d = 0; d < 16; d++) {
            O[d][0] *= c0; O[d][1] *= c0;
            O[d][2] *= c1; O[d][3] *= c1;
        }
        float ps0 = 0.f, ps1 = 0.f;
        #pragma unroll
        for (int i = 0; i < 8; i++) {
            sa[i][0] = fexp(sa[i][0] - mn0); ps0 += sa[i][0];
            sa[i][1] = fexp(sa[i][1] - mn0); ps0 += sa[i][1];
            sa[i][2] = fexp(sa[i][2] - mn1); ps1 += sa[i][2];
            sa[i][3] = fexp(sa[i][3] - mn1); ps1 += sa[i][3];
        }
        ps0 += __shfl_xor_sync(0xffffffffu, ps0, 1);
        ps0 += __shfl_xor_sync(0xffffffffu, ps0, 2);
        ps1 += __shfl_xor_sync(0xffffffffu, ps1, 1);
        ps1 += __shfl_xor_sync(0xffffffffu, ps1, 2);
        l0s = l0s * c0 + ps0;  m0s = mn0;
        l1s = l1s * c1 + ps1;  m1s = mn1;

        uint32_t pf[4][4];
        #pragma unroll
        for (int t = 0; t < 4; t++) {
            __half2 h0 = __floats2half2_rn(sa[2*t][0],   sa[2*t][1]);
            __half2 h1 = __floats2half2_rn(sa[2*t][2],   sa[2*t][3]);
            __half2 h2 = __floats2half2_rn(sa[2*t+1][0], sa[2*t+1][1]);
            __half2 h3 = __floats2half2_rn(sa[2*t+1][2], sa[2*t+1][3]);
            pf[t][0] = *(uint32_t*)&h0; pf[t][1] = *(uint32_t*)&h1;
            pf[t][2] = *(uint32_t*)&h2; pf[t][3] = *(uint32_t*)&h3;
        }

        const uint32_t vst = st + 16384;
        #pragma unroll
        for (int dg = 0; dg < 8; dg++) {
            const uint32_t vrow = vst + (uint32_t)(dg*16 + bn) * 128;
            #pragma unroll
            for (int t = 0; t < 4; t++) {
                uint32_t bf[4];
                ldm4(bf, vrow + (uint32_t)(((2*t + bko) ^ bxor) << 4));
                mma_hf(O[2*dg],   pf[t], bf[0], bf[1]);
                mma_hf(O[2*dg+1], pf[t], bf[2], bf[3]);
            }
        }
        __syncthreads();
        if (kt + 2 < 32) load_stage(kt + 2, kt & 1);
        CP_COMMIT();
    }

    const float i0 = 1.f / l0s, i1 = 1.f / l1s;
    const int r0 = m0 + w * 16 + (l >> 2);
    #pragma unroll
    for (int d = 0; d < 16; d++) {
        const int col = h * HDIM + d * 8 + 2 * (l & 3);
        __half2 p0 = __floats2half2_rn(O[d][0] * i0, O[d][1] * i0);
        __half2 p1 = __floats2half2_rn(O[d][2] * i1, O[d][3] * i1);
        *(uint32_t*)&ob[(long)r0 * DIM + col]       = *(uint32_t*)&p0;
        *(uint32_t*)&ob[(long)(r0 + 8) * DIM + col] = *(uint32_t*)&p1;
    }
}

// ---------------- combine ----------------
__global__ __launch_bounds__(256) void combine_kernel(
    const fp16* __restrict__ o1, const fp16* __restrict__ o2,
    const float* __restrict__ lam, fp16* __restrict__ oa)
{
    long i = (long)blockIdx.x * 256 + threadIdx.x;
    int h = (int)((i * 2) % DIM) / HDIM;
    float lm = lam[h];
    __half2 a = ((const __half2*)o1)[i];
    __half2 b = ((const __half2*)o2)[i];
    float2 af = __half22float2(a), bf = __half22float2(b);
    __half2 r = __floats2half2_rn(af.x - lm * bf.x, af.y - lm * bf.y);
    ((__half2*)oa)[i] = r;
}

// ---------------- batched QKV weight transpose ----------------
__global__ __launch_bounds__(256) void wt5_kernel(
    const float* __restrict__ w0, const float* __restrict__ w1,
    const float* __restrict__ w2, const float* __restrict__ w3,
    const float* __restrict__ w4, fp16* __restrict__ outb)
{
    const int z = blockIdx.z;
    const int m = z >> 4, h = z & 15;
    const float* in = (m == 0 ? w0 : m == 1 ? w1 : m == 2 ? w2 : m == 3 ? w3 : w4)
                    + (long)h * DIM * HDIM;
    fp16* oh = outb + (long)m * DIM * DIM + (long)h * HDIM * DIM;
    const int c0 = blockIdx.x * 32, r0 = blockIdx.y * 32;
    __shared__ float t[32][33];
    const int tx = threadIdx.x & 31, ty = threadIdx.x >> 5;
    #pragma unroll
    for (int i = 0; i < 4; i++)
        t[ty + 8*i][tx] = in[(long)(r0 + ty + 8*i) * HDIM + c0 + tx];
    __syncthreads();
    #pragma unroll
    for (int i = 0; i < 4; i++)
        oh[(long)(c0 + ty + 8*i) * DIM + r0 + tx] = __float2half(t[tx][ty + 8*i]);
}

// ---------------- fp16 -> fp16 transpose ----------------
__global__ __launch_bounds__(256) void transpose_hh(const fp16* __restrict__ in,
                                                    fp16* __restrict__ oh,
                                                    int R, int C) {
    const int c0 = blockIdx.x * 32, r0 = blockIdx.y * 32;
    __shared__ fp16 t[32][34];
    const int tx = threadIdx.x & 31, ty = threadIdx.x >> 5;
    #pragma unroll
    for (int i = 0; i < 4; i++)
        t[ty + 8*i][tx] = in[(long)(r0 + ty + 8*i) * C + c0 + tx];
    __syncthreads();
    #pragma unroll
    for (int i = 0; i < 4; i++)
        oh[(long)(c0 + ty + 8*i) * R + r0 + tx] = t[tx][ty + 8*i];
}

// ---------------- generic transpose fp32->fp16 ----------------
__global__ __launch_bounds__(256) void transpose_half2(
    const float* __restrict__ inA, const float* __restrict__ inB,
    fp16* __restrict__ outb, int R, int C)
{
    const int z = blockIdx.z;
    const float* in = (z == 0) ? inA : inB;
    fp16* oh = outb + (long)z * R * C;
    const int c0 = blockIdx.x * 32, r0 = blockIdx.y * 32;
    __shared__ float t[32][33];
    const int tx = threadIdx.x & 31, ty = threadIdx.x >> 5;
    #pragma unroll
    for (int i = 0; i < 4; i++)
        t[ty + 8*i][tx] = in[(long)(r0 + ty + 8*i) * C + c0 + tx];
    __syncthreads();
    #pragma unroll
    for (int i = 0; i < 4; i++)
        oh[(long)(c0 + ty + 8*i) * R + r0 + tx] = __float2half(t[tx][ty + 8*i]);
}

// ---------------- RMSNorm ----------------
__global__ __launch_bounds__(256) void rmsnorm_kernel(const float* __restrict__ x,
                                                      const float* __restrict__ g,
                                                      float* __restrict__ yf,
                                                      fp16* __restrict__ ya) {
    __shared__ float sh[8];
    const long row = blockIdx.x;
    const float* xr = x + row * (long)DIM;
    float v[8], ss = 0.f;
    #pragma unroll
    for (int i = 0; i < 8; i++) { v[i] = xr[threadIdx.x + 256*i]; ss += v[i]*v[i]; }
    #pragma unroll
    for (int o = 16; o; o >>= 1) ss += __shfl_xor_sync(0xffffffffu, ss, o);
    if ((threadIdx.x & 31) == 0) sh[threadIdx.x >> 5] = ss;
    __syncthreads();
    float tot = 0.f;
    #pragma unroll
    for (int i = 0; i < 8; i++) tot += sh[i];
    const float sc = rsqrtf(tot * (1.0f / DIM) + EPSV);
    #pragma unroll
    for (int i = 0; i < 8; i++) {
        int c = threadIdx.x + 256*i;
        float y = v[i] * sc * g[c];
        long o = row * (long)DIM + c;
        if (yf) yf[o] = y;
        ya[o] = __float2half(y);
    }
}

// ---------------- lambda ----------------
__global__ void lambda_kernel(const float* __restrict__ lq1, const float* __restrict__ lk1,
                              const float* __restrict__ lq2, const float* __restrict__ lk2,
                              float* __restrict__ lam) {
    __shared__ float s1[128], s2[128];
    int h = blockIdx.x, t = threadIdx.x;
    int i = h * HDIM + t;
    s1[t] = lq1[i] * lk1[i];
    s2[t] = lq2[i] * lk2[i];
    __syncthreads();
    for (int o = 64; o; o >>= 1) {
        if (t < o) { s1[t] += s1[t+o]; s2[t] += s2[t+o]; }
        __syncthreads();
    }
    if (t == 0) lam[h] = expf(s1[0]) - expf(s2[0]) + LAMB0;
}

// ---------------- launcher ----------------
extern "C" void kernel_launch(void* const* d_in, const int* in_sizes, int n_in,
                              void* d_out, int out_size) {
    (void)in_sizes; (void)n_in; (void)out_size;
    const float* x   = (const float*)d_in[0];
    const float* gn  = (const float*)d_in[1];
    const float* Wq1 = (const float*)d_in[2];
    const float* Wq2 = (const float*)d_in[3];
    const float* Wk1 = (const float*)d_in[4];
    const float* Wk2 = (const float*)d_in[5];
    const float* Wv  = (const float*)d_in[6];
    const float* lq1 = (const float*)d_in[7];
    const float* lk1 = (const float*)d_in[8];
    const float* lq2 = (const float*)d_in[9];
    const float* lk2 = (const float*)d_in[10];
    const float* Wo  = (const float*)d_in[11];
    const float* W1  = (const float*)d_in[12];
    const float* W2  = (const float*)d_in[13];
    const float* W3  = (const float*)d_in[14];
    float* out = (float*)d_out;

    const int SMEM  = 3 * 36864;         // 110592 (GEMM, KC=64, 3 stages)
    const int FSMEM = 32768 + 2 * 32768; // 98304 (flash)
    cudaFuncSetAttribute(mma_gemm<0>, cudaFuncAttributeMaxDynamicSharedMemorySize, SMEM);
    cudaFuncSetAttribute(mma_gemm<2>, cudaFuncAttributeMaxDynamicSharedMemorySize, SMEM);
    cudaFuncSetAttribute(mma_gemm<3>, cudaFuncAttributeMaxDynamicSharedMemorySize, SMEM);
    cudaFuncSetAttribute(flash_both, cudaFuncAttributeMaxDynamicSharedMemorySize, FSMEM);

#define SYM(v, s) cudaGetSymbolAddress((void**)&v, s)
    float *h0f, *hf, *lam;
    SYM(h0f, g_h0f); SYM(hf, g_hf); SYM(lam, g_lam);
    fp16 *h0a,*za,*qk,*vt,*o1,*o2,*oa,*g1h,*ua;
    fp16 *fwqkv,*fwo,*fw12,*fw3;
    SYM(h0a, g_h0a); SYM(za, g_za); SYM(qk, g_qk); SYM(vt, g_vt);
    SYM(o1, g_o1); SYM(o2, g_o2); SYM(oa, g_oa); SYM(g1h, g_g1h); SYM(ua, g_ua);
    SYM(fwqkv, g_fwqkv); SYM(fwo, g_fwo); SYM(fw12, g_fw12); SYM(fw3, g_fw3);
#undef SYM

    const long SD = (long)SEQ * DIM;
    const long DD = (long)DIM * DIM;
    fp16* q1 = qk;
    fp16* q2 = qk + SD;
    fp16* k1 = qk + 2 * SD;
    fp16* k2 = qk + 3 * SD;
    fp16* vr = qk + 4 * SD;
    fp16* fw1 = fw12;
    fp16* fw2 = fw12 + (long)DIM * HIDN;

    // 1) batched QKV weight transpose
    dim3 g5(HDIM/32, DIM/32, 5 * NH);
    wt5_kernel<<<g5, 256>>>(Wq1, Wq2, Wk1, Wk2, Wv, fwqkv);
    // 2) h0 = rmsnorm(x)
    rmsnorm_kernel<<<SEQ, 256>>>(x, gn, h0f, h0a);
    // 3) lambda
    lambda_kernel<<<NH, 128>>>(lq1, lk1, lq2, lk2, lam);
    // 4) q1,q2,k1,k2,V batched projection (z = 5)
    dim3 gproj(DIM/128, SEQ/128, 5);
    mma_gemm<2><<<gproj, 256, SMEM>>>(h0a, DIM, 0, fwqkv, DIM, DD, nullptr, nullptr, nullptr, qk, DIM, SD, DIM, 1.f);
    // 5) V^T
    dim3 gtV(DIM/32, SEQ/32, 1);
    transpose_hh<<<gtV, 256>>>(vr, vt, SEQ, DIM);
    // 6) both flash branches
    dim3 gfl(SEQ/128, NH, 2);
    flash_both<<<gfl, 256, FSMEM>>>(q1, q2, k1, k2, vt, o1, o2);

    // combine
    combine_kernel<<<(SEQ * DIM / 2) / 256, 256>>>(o1, o2, lam, oa);

    // Wo transpose + h = O @ Wo + h0
    dim3 gtO(DIM/32, DIM/32, 1);
    transpose_half2<<<gtO, 256>>>(Wo, Wo, fwo, DIM, DIM);
    dim3 gwo(DIM/128, SEQ/128, 1);
    mma_gemm<0><<<gwo, 256, SMEM>>>(oa, DIM, 0, fwo, DIM, 0, hf, h0f, nullptr, nullptr, DIM, 0, DIM, 1.f);

    // z = rmsnorm(h)
    rmsnorm_kernel<<<SEQ, 256>>>(hf, gn, nullptr, za);

    // FFN weight transposes + GEMMs
    dim3 gt12(HIDN/32, DIM/32, 2);
    transpose_half2<<<gt12, 256>>>(W1, W2, fw12, DIM, HIDN);
    dim3 gt3(DIM/32, HIDN/32, 1);
    transpose_half2<<<gt3, 256>>>(W3, W3, fw3, HIDN, DIM);

    dim3 gffn(HIDN/128, SEQ/128, 1);
    mma_gemm<2><<<gffn, 256, SMEM>>>(za, DIM, 0, fw1, DIM, 0, nullptr, nullptr, nullptr, g1h, HIDN, 0, DIM, 1.f);
    mma_gemm<3><<<gffn, 256, SMEM>>>(za, DIM, 0, fw2, DIM, 0, nullptr, nullptr, g1h, ua, HIDN, 0, DIM, 1.f);

    dim3 gw3(DIM/128, SEQ/128, 1);
    mma_gemm<0><<<gw3, 256, SMEM>>>(ua, HIDN, 0, fw3, HIDN, 0, out, hf, nullptr, nullptr, DIM, 0, HIDN, 1.f);
}